// round 14
// baseline (speedup 1.0000x reference)
#include <cuda_runtime.h>
#include <cuda_fp16.h>
#include <math.h>

#define CC   256
#define CQ   32
#define NPIX 4096
#define EPSB 1e-5f
#define KW   2304
#define ESH  8.0f

#define PH 20              // half2 tile pad: row stride 80B (16B-aligned, LDSM conflict-free)
#define PT2 68             // energy P'-staging row stride (u32): 68 mod 32 = 4 -> conflict-free

// ---------------- scratch ----------------
__device__ __align__(16) __half g_xt1[NPIX * CC];
__device__ __align__(16) __half g_xt2[NPIX * CC];
__device__ __align__(16) __half g_xfh1[NPIX * CC];
__device__ __align__(16) __half g_xfh2[NPIX * CC];
__device__ __align__(16) __half g_qh1[NPIX * CQ];
__device__ __align__(16) __half g_kh1[NPIX * CQ];
__device__ __align__(16) __half g_qh2[NPIX * CQ];
__device__ __align__(16) __half g_kh2[NPIX * CQ];
__device__ __align__(16) __half g_vh1[CC * NPIX];
__device__ __align__(16) __half g_vh2[CC * NPIX];
__device__ __align__(16) __half g_p1[(size_t)NPIX * NPIX];
__device__ __align__(16) __half g_p2[(size_t)NPIX * NPIX];
__device__ float g_ps1[NPIX * 32];
__device__ float g_ps2[NPIX * 32];
__device__ __align__(16) __half g_wx1h[CC * KW];
__device__ __align__(16) __half g_wy1h[CC * KW];
__device__ __align__(16) __half g_wx2h[CC * KW];
__device__ __align__(16) __half g_wy2h[CC * KW];

// ---------------- helpers ----------------
__device__ __forceinline__ void mma16h(float* c, const unsigned* a, const unsigned* b) {
    asm volatile(
        "mma.sync.aligned.m16n8k16.row.col.f32.f16.f16.f32 "
        "{%0,%1,%2,%3}, {%4,%5,%6,%7}, {%8,%9}, {%0,%1,%2,%3};"
        : "+f"(c[0]), "+f"(c[1]), "+f"(c[2]), "+f"(c[3])
        : "r"(a[0]), "r"(a[1]), "r"(a[2]), "r"(a[3]), "r"(b[0]), "r"(b[1]));
}
__device__ __forceinline__ unsigned h2u(float lo, float hi) {
    __half2 h = __floats2half2_rn(lo, hi);
    return *reinterpret_cast<unsigned*>(&h);
}
__device__ __forceinline__ void ldsm4(unsigned* r, unsigned addr) {
    asm volatile("ldmatrix.sync.aligned.m8n8.x4.shared.b16 {%0,%1,%2,%3}, [%4];"
                 : "=r"(r[0]), "=r"(r[1]), "=r"(r[2]), "=r"(r[3]) : "r"(addr));
}
__device__ __forceinline__ void ldsm2(unsigned* r, unsigned addr) {
    asm volatile("ldmatrix.sync.aligned.m8n8.x2.shared.b16 {%0,%1}, [%2];"
                 : "=r"(r[0]), "=r"(r[1]) : "r"(addr));
}
__device__ __forceinline__ unsigned smem_u32(const void* p) {
    return (unsigned)__cvta_generic_to_shared(p);
}

// ---------------------------------------------------------------------------
// prep: conv-weight pack (blocks 0..9215) + x transpose (blocks 9216..9727)
// ---------------------------------------------------------------------------
__global__ void prep_kernel(const float* __restrict__ s0, const float* __restrict__ s1,
                            const float* __restrict__ s2, const float* __restrict__ s3,
                            __half* __restrict__ d0, __half* __restrict__ d1,
                            __half* __restrict__ d2, __half* __restrict__ d3,
                            const float* __restrict__ x1, const float* __restrict__ x2,
                            __half* __restrict__ xo1, __half* __restrict__ xo2)
{
    const int bid = blockIdx.x;
    const int tid = threadIdx.x;
    if (bid < 9216) {
        const int y = bid / 2304, xb = bid % 2304;
        const float* s = (y == 0) ? s0 : (y == 1) ? s1 : (y == 2) ? s2 : s3;
        __half* d = (y == 0) ? d0 : (y == 1) ? d1 : (y == 2) ? d2 : d3;
        int t = xb * 256 + tid;
        int m = t / KW, r = t % KW;
        d[t] = __float2half(s[m * KW + (r & 255) * 9 + (r >> 8)]);
    } else {
        __shared__ __align__(16) __half T[64 * 72];
        const int idx = bid - 9216;
        const int z = idx >> 8;
        const int cy = (idx >> 6) & 3;
        const int xb = idx & 63;
        const float* x = z ? x2 : x1;
        __half* o = z ? xo2 : xo1;
        const int c0 = cy * 64, p0 = xb * 64;
        #pragma unroll
        for (int it = 0; it < 16; it++) {
            int i2 = tid + it * 256;
            int c = i2 >> 6, p = i2 & 63;
            T[p * 72 + c] = __float2half(x[(c0 + c) * NPIX + p0 + p]);
        }
        __syncthreads();
        #pragma unroll
        for (int k = 0; k < 2; k++) {
            int i2 = tid + k * 256;
            int p = i2 >> 3, u = i2 & 7;
            *(uint4*)&o[(size_t)(p0 + p) * CC + c0 + u * 8] = *(uint4*)&T[p * 72 + u * 8];
        }
    }
}

// ---------------------------------------------------------------------------
// Sobel fp16 (batched z=2) — unchanged (working).
// ---------------------------------------------------------------------------
__global__ void __launch_bounds__(256, 2) sobel_fp16(
    const __half* __restrict__ xt1, const __half* __restrict__ wx1,
    const __half* __restrict__ wy1, const float* __restrict__ bn1x,
    const float* __restrict__ bn1y, __half* __restrict__ o1,
    const __half* __restrict__ xt2, const __half* __restrict__ wx2,
    const __half* __restrict__ wy2, const float* __restrict__ bn2x,
    const float* __restrict__ bn2y, __half* __restrict__ o2)
{
    __shared__ __align__(16) unsigned Ax[2][64 * PH];
    __shared__ __align__(16) unsigned Ay[2][64 * PH];
    __shared__ __align__(16) unsigned Bt[2][128 * PH];

    const int z = blockIdx.z;
    const __half* xt  = z ? xt2 : xt1;
    const __half* wxh = z ? wx2 : wx1;
    const __half* wyh = z ? wy2 : wy1;
    const float* bnx = z ? bn2x : bn1x;
    const float* bny = z ? bn2y : bn1y;
    __half* out = z ? o2 : o1;

    const int tid = threadIdx.x;
    const int lane = tid & 31, wid = tid >> 5;
    const int g = lane >> 2, tig = lane & 3;
    const int m_off = (wid >> 2) * 32, n_off = (wid & 3) * 32;
    const int m0 = blockIdx.y * 64, n0 = blockIdx.x * 128;

    const int lrowA = lane & 15, lkofA = (lane & 16) ? 4 : 0;
    const int lrowB = lane & 7,  lkofB = (lane & 8) ? 4 : 0;
    const unsigned sAx0 = smem_u32(&Ax[0][0]);
    const unsigned sAy0 = smem_u32(&Ay[0][0]);
    const unsigned sBt0 = smem_u32(&Bt[0][0]);

    float accx[2][4][4] = {};
    float accy[2][4][4] = {};

    const int am = tid >> 2, ak = tid & 3;
    const int bn = tid & 127, khb = (tid >> 7) * 8;
    const int pix = n0 + bn;
    const int py = pix >> 6, px = pix & 63;

    uint4 rAx, rAy, rB0, rB1;

    #define SB_LOAD(kt) { \
        rAx = *(const uint4*)&wxh[(m0 + am) * KW + (kt) + ak * 8]; \
        rAy = *(const uint4*)&wyh[(m0 + am) * KW + (kt) + ak * 8]; \
        const int tap = (kt) >> 8; \
        const int dy = tap / 3 - 1, dx = tap % 3 - 1; \
        const int cibase = (kt) & 255; \
        const int yy = py + dy, xx = px + dx; \
        if (yy >= 0 && yy < 64 && xx >= 0 && xx < 64) { \
            const __half* sp = xt + (size_t)(yy * 64 + xx) * CC + cibase + khb * 2; \
            rB0 = *(const uint4*)&sp[0]; \
            rB1 = *(const uint4*)&sp[8]; \
        } else { \
            rB0 = make_uint4(0u, 0u, 0u, 0u); \
            rB1 = make_uint4(0u, 0u, 0u, 0u); \
        } }

    #define SB_STORE(buf) { \
        *(uint4*)&Ax[buf][am * PH + ak * 4] = rAx; \
        *(uint4*)&Ay[buf][am * PH + ak * 4] = rAy; \
        *(uint4*)&Bt[buf][bn * PH + khb] = rB0; \
        *(uint4*)&Bt[buf][bn * PH + khb + 4] = rB1; }

    SB_LOAD(0);
    SB_STORE(0);
    __syncthreads();

    int buf = 0;
    for (int c = 0; c < KW / 32; c++) {
        const bool more = (c + 1 < KW / 32);
        if (more) { const int ktn = (c + 1) * 32; SB_LOAD(ktn); }

        const unsigned bufoff = buf * 64 * PH * 4;
        const unsigned bufoffB = buf * 128 * PH * 4;
        #pragma unroll
        for (int ks = 0; ks < 2; ks++) {
            const int k0h = ks * 8;
            unsigned ax[2][4], ay[2][4], b[4][2];
            #pragma unroll
            for (int mf = 0; mf < 2; mf++) {
                unsigned ro = ((m_off + mf * 16 + lrowA) * PH + k0h + lkofA) * 4;
                ldsm4(ax[mf], sAx0 + bufoff + ro);
                ldsm4(ay[mf], sAy0 + bufoff + ro);
            }
            #pragma unroll
            for (int nf = 0; nf < 4; nf++) {
                unsigned ro = ((n_off + nf * 8 + lrowB) * PH + k0h + lkofB) * 4;
                ldsm2(b[nf], sBt0 + bufoffB + ro);
            }
            #pragma unroll
            for (int mf = 0; mf < 2; mf++)
                #pragma unroll
                for (int nf = 0; nf < 4; nf++) {
                    mma16h(accx[mf][nf], ax[mf], b[nf]);
                    mma16h(accy[mf][nf], ay[mf], b[nf]);
                }
        }
        if (more) SB_STORE(buf ^ 1);
        __syncthreads();
        buf ^= 1;
    }

    __half* T = (__half*)&Bt[0][0];
    #pragma unroll
    for (int mf = 0; mf < 2; mf++) {
        int ch0 = m_off + mf * 16 + g;
        int ch1 = ch0 + 8;
        int r0 = m0 + ch0, r1 = m0 + ch1;
        float ivx0 = bnx[r0] * rsqrtf(bnx[768 + r0] + EPSB);
        float ivx1 = bnx[r1] * rsqrtf(bnx[768 + r1] + EPSB);
        float bx0 = bnx[256 + r0], bx1 = bnx[256 + r1];
        float mx0 = bnx[512 + r0], mx1 = bnx[512 + r1];
        float ivy0 = bny[r0] * rsqrtf(bny[768 + r0] + EPSB);
        float ivy1 = bny[r1] * rsqrtf(bny[768 + r1] + EPSB);
        float by0 = bny[256 + r0], by1 = bny[256 + r1];
        float my0 = bny[512 + r0], my1 = bny[512 + r1];
        #pragma unroll
        for (int nf = 0; nf < 4; nf++) {
            int col = n_off + nf * 8 + 2 * tig;
            float gx, gy;
            gx = (accx[mf][nf][0] - mx0) * ivx0 + bx0;
            gy = (accy[mf][nf][0] - my0) * ivy0 + by0;
            T[col * 72 + ch0] = __float2half(sqrtf(gx * gx + gy * gy));
            gx = (accx[mf][nf][1] - mx0) * ivx0 + bx0;
            gy = (accy[mf][nf][1] - my0) * ivy0 + by0;
            T[(col + 1) * 72 + ch0] = __float2half(sqrtf(gx * gx + gy * gy));
            gx = (accx[mf][nf][2] - mx1) * ivx1 + bx1;
            gy = (accy[mf][nf][2] - my1) * ivy1 + by1;
            T[col * 72 + ch1] = __float2half(sqrtf(gx * gx + gy * gy));
            gx = (accx[mf][nf][3] - mx1) * ivx1 + bx1;
            gy = (accy[mf][nf][3] - my1) * ivy1 + by1;
            T[(col + 1) * 72 + ch1] = __float2half(sqrtf(gx * gx + gy * gy));
        }
    }
    __syncthreads();
    #pragma unroll
    for (int k = 0; k < 4; k++) {
        int idx = tid + k * 256;
        int p = idx >> 3, u = idx & 7;
        *(uint4*)&out[(size_t)(n0 + p) * CC + m0 + u * 8] = *(uint4*)&T[p * 72 + u * 8];
    }
}

// ---------------------------------------------------------------------------
// proj merged (6 GEMMs in one launch): grid (32, 12) — unchanged.
// ---------------------------------------------------------------------------
struct ProjAll {
    const float* A[6];
    const __half* B[6];
    const float* bias[6];
    __half* out[6];
};

__global__ void __launch_bounds__(256, 2) proj_all(ProjAll args)
{
    __shared__ __align__(16) unsigned As[2][64 * PH];
    __shared__ __align__(16) unsigned Bt[2][128 * PH];

    const int yb = blockIdx.y;
    const int zi = (yb < 4) ? yb : 4 + ((yb - 4) >> 2);
    const int my = (yb < 4) ? 0 : ((yb - 4) & 3);
    const int M = (yb < 4) ? CQ : CC;
    const float* A = args.A[zi];
    const __half* B = args.B[zi];
    const float* bias = args.bias[zi];
    __half* out = args.out[zi];

    const int tid = threadIdx.x;
    const int lane = tid & 31, wid = tid >> 5;
    const int g = lane >> 2, tig = lane & 3;
    const int m_off = (wid >> 2) * 32, n_off = (wid & 3) * 32;
    const int m0 = my * 64, n0 = blockIdx.x * 128;

    const int lrowA = lane & 15, lkofA = (lane & 16) ? 4 : 0;
    const int lrowB = lane & 7,  lkofB = (lane & 8) ? 4 : 0;
    const unsigned sAs0 = smem_u32(&As[0][0]);
    const unsigned sBt0 = smem_u32(&Bt[0][0]);

    float acc[2][4][4] = {};

    const int am = tid >> 2, ak = tid & 3;
    const int brow = tid >> 2, bu = tid & 3;

    unsigned rA[4];
    uint4 rB0, rB1;

    #define PJ_LOAD(kt) { \
        if (m0 + am < M) { \
            float4 a0 = *(const float4*)&A[(m0 + am) * 256 + (kt) + ak * 8]; \
            float4 a1 = *(const float4*)&A[(m0 + am) * 256 + (kt) + ak * 8 + 4]; \
            rA[0] = h2u(a0.x, a0.y); rA[1] = h2u(a0.z, a0.w); \
            rA[2] = h2u(a1.x, a1.y); rA[3] = h2u(a1.z, a1.w); \
        } else { rA[0] = rA[1] = rA[2] = rA[3] = 0u; } \
        rB0 = *(const uint4*)&B[(size_t)(n0 + brow) * CC + (kt) + bu * 8]; \
        rB1 = *(const uint4*)&B[(size_t)(n0 + brow + 64) * CC + (kt) + bu * 8]; }

    #define PJ_STORE(buf) { \
        *(uint4*)&As[buf][am * PH + ak * 4] = make_uint4(rA[0], rA[1], rA[2], rA[3]); \
        *(uint4*)&Bt[buf][brow * PH + bu * 4] = rB0; \
        *(uint4*)&Bt[buf][(brow + 64) * PH + bu * 4] = rB1; }

    PJ_LOAD(0);
    PJ_STORE(0);
    __syncthreads();

    int buf = 0;
    for (int c = 0; c < 8; c++) {
        const bool more = (c + 1 < 8);
        if (more) { const int ktn = (c + 1) * 32; PJ_LOAD(ktn); }

        const unsigned bufoff = buf * 64 * PH * 4;
        const unsigned bufoffB = buf * 128 * PH * 4;
        #pragma unroll
        for (int ks = 0; ks < 2; ks++) {
            const int k0h = ks * 8;
            unsigned a[2][4], b[4][2];
            #pragma unroll
            for (int mf = 0; mf < 2; mf++) {
                unsigned ro = ((m_off + mf * 16 + lrowA) * PH + k0h + lkofA) * 4;
                ldsm4(a[mf], sAs0 + bufoff + ro);
            }
            #pragma unroll
            for (int nf = 0; nf < 4; nf++) {
                unsigned ro = ((n_off + nf * 8 + lrowB) * PH + k0h + lkofB) * 4;
                ldsm2(b[nf], sBt0 + bufoffB + ro);
            }
            #pragma unroll
            for (int mf = 0; mf < 2; mf++)
                #pragma unroll
                for (int nf = 0; nf < 4; nf++)
                    mma16h(acc[mf][nf], a[mf], b[nf]);
        }
        if (more) PJ_STORE(buf ^ 1);
        __syncthreads();
        buf ^= 1;
    }

    if (M == CQ) {
        #pragma unroll
        for (int mf = 0; mf < 2; mf++) {
            int r0 = m0 + m_off + mf * 16 + g;
            int r1 = r0 + 8;
            #pragma unroll
            for (int nf = 0; nf < 4; nf++) {
                int col = n0 + n_off + nf * 8 + 2 * tig;
                if (r0 < M) {
                    float b0 = bias[r0];
                    out[(size_t)col * CQ + r0]       = __float2half(acc[mf][nf][0] + b0);
                    out[(size_t)(col + 1) * CQ + r0] = __float2half(acc[mf][nf][1] + b0);
                }
                if (r1 < M) {
                    float b1 = bias[r1];
                    out[(size_t)col * CQ + r1]       = __float2half(acc[mf][nf][2] + b1);
                    out[(size_t)(col + 1) * CQ + r1] = __float2half(acc[mf][nf][3] + b1);
                }
            }
        }
    } else {
        #pragma unroll
        for (int mf = 0; mf < 2; mf++) {
            int r0 = m0 + m_off + mf * 16 + g;
            int r1 = r0 + 8;
            float b0 = bias[r0];
            float b1 = bias[r1];
            #pragma unroll
            for (int nf = 0; nf < 4; nf++) {
                int col = n0 + n_off + nf * 8 + 2 * tig;
                *(unsigned*)&out[(size_t)r0 * NPIX + col] =
                    h2u(acc[mf][nf][0] + b0, acc[mf][nf][1] + b0);
                *(unsigned*)&out[(size_t)r1 * NPIX + col] =
                    h2u(acc[mf][nf][2] + b1, acc[mf][nf][3] + b1);
            }
        }
    }
}

// ---------------------------------------------------------------------------
// energy+exp (batched z=2): P' = exp(q·k - ESH) fp16 + partial row sums.
// Output staged through smem for fully coalesced uint4 stores.
// grid (32, 64, 2), block 256.
// ---------------------------------------------------------------------------
__global__ void energy_exp(const __half* __restrict__ q1, const __half* __restrict__ k1,
                           __half* __restrict__ p1, float* __restrict__ ps1,
                           const __half* __restrict__ q2, const __half* __restrict__ k2,
                           __half* __restrict__ p2, float* __restrict__ ps2)
{
    __shared__ __align__(16) unsigned Qh[64 * PH];
    __shared__ __align__(16) unsigned Kh[128 * PH];
    __shared__ __align__(16) unsigned Pt[64 * PT2];
    __shared__ float rsum[64][4];

    const int z = blockIdx.z;
    const __half* q = z ? q2 : q1;
    const __half* k = z ? k2 : k1;
    __half* pm = z ? p2 : p1;
    float* ps = z ? ps2 : ps1;

    const int tid = threadIdx.x;
    const int lane = tid & 31, wid = tid >> 5;
    const int g = lane >> 2, tig = lane & 3;
    const int m_off = (wid >> 2) * 32, n_off = (wid & 3) * 32;
    const int kc = wid & 3;
    const int m0 = blockIdx.y * 64, n0 = blockIdx.x * 128;

    const int lrowA = lane & 15, lkofA = (lane & 16) ? 4 : 0;
    const int lrowB = lane & 7,  lkofB = (lane & 8) ? 4 : 0;
    const unsigned sQ = smem_u32(&Qh[0]);
    const unsigned sK = smem_u32(&Kh[0]);

    {
        int m = tid >> 2, u = tid & 3;
        *(uint4*)&Qh[m * PH + u * 4] = *(const uint4*)&q[(size_t)(m0 + m) * CQ + u * 8];
    }
    #pragma unroll
    for (int kk = 0; kk < 2; kk++) {
        int idx = tid + kk * 256;
        int n = idx >> 2, u = idx & 3;
        *(uint4*)&Kh[n * PH + u * 4] = *(const uint4*)&k[(size_t)(n0 + n) * CQ + u * 8];
    }
    __syncthreads();

    float acc[2][4][4] = {};
    #pragma unroll
    for (int ks = 0; ks < 2; ks++) {
        const int k0h = ks * 8;
        unsigned a[2][4], b[4][2];
        #pragma unroll
        for (int mf = 0; mf < 2; mf++) {
            unsigned ro = ((m_off + mf * 16 + lrowA) * PH + k0h + lkofA) * 4;
            ldsm4(a[mf], sQ + ro);
        }
        #pragma unroll
        for (int nf = 0; nf < 4; nf++) {
            unsigned ro = ((n_off + nf * 8 + lrowB) * PH + k0h + lkofB) * 4;
            ldsm2(b[nf], sK + ro);
        }
        #pragma unroll
        for (int mf = 0; mf < 2; mf++)
            #pragma unroll
            for (int nf = 0; nf < 4; nf++)
                mma16h(acc[mf][nf], a[mf], b[nf]);
    }

    // exp -> smem staging tile (conflict-free 4B stores), row sums in regs
    float s[2][2] = {};
    #pragma unroll
    for (int mf = 0; mf < 2; mf++) {
        int lr0 = m_off + mf * 16 + g;
        int lr1 = lr0 + 8;
        #pragma unroll
        for (int nf = 0; nf < 4; nf++) {
            int cu = (n_off >> 1) + nf * 4 + tig;   // u32 column in [0,64)
            float p0 = __expf(acc[mf][nf][0] - ESH);
            float p1 = __expf(acc[mf][nf][1] - ESH);
            float p2 = __expf(acc[mf][nf][2] - ESH);
            float p3 = __expf(acc[mf][nf][3] - ESH);
            s[mf][0] += p0 + p1;
            s[mf][1] += p2 + p3;
            Pt[lr0 * PT2 + cu] = h2u(p0, p1);
            Pt[lr1 * PT2 + cu] = h2u(p2, p3);
        }
    }
    #pragma unroll
    for (int mf = 0; mf < 2; mf++) {
        #pragma unroll
        for (int j = 0; j < 2; j++) {
            s[mf][j] += __shfl_xor_sync(0xffffffffu, s[mf][j], 1);
            s[mf][j] += __shfl_xor_sync(0xffffffffu, s[mf][j], 2);
        }
    }
    if (tig == 0) {
        #pragma unroll
        for (int mf = 0; mf < 2; mf++) {
            int lr0 = m_off + mf * 16 + g;
            rsum[lr0][kc] = s[mf][0];
            rsum[lr0 + 8][kc] = s[mf][1];
        }
    }
    __syncthreads();

    // coalesced writeback: 64 rows x 16 uint4
    #pragma unroll
    for (int kk = 0; kk < 4; kk++) {
        int idx = tid + kk * 256;
        int r = idx >> 4, u = idx & 15;
        *(uint4*)&pm[(size_t)(m0 + r) * NPIX + n0 + u * 8] = *(uint4*)&Pt[r * PT2 + u * 4];
    }
    if (tid < 64) {
        ps[(size_t)(m0 + tid) * 32 + blockIdx.x] =
            rsum[tid][0] + rsum[tid][1] + rsum[tid][2] + rsum[tid][3];
    }
}

// ---------------------------------------------------------------------------
// av fp16 (batched z=2): m 128 x n 128, lsum folded into prologue — unchanged.
// ---------------------------------------------------------------------------
__global__ void __launch_bounds__(256, 2) av_fp16(
    const __half* __restrict__ v1, const __half* __restrict__ p1,
    const float* __restrict__ xq1, const float* __restrict__ gm1,
    const float* __restrict__ ps1,
    const __half* __restrict__ v2, const __half* __restrict__ p2,
    const float* __restrict__ xq2, const float* __restrict__ gm2,
    const float* __restrict__ ps2,
    float* __restrict__ outbase)
{
    __shared__ __align__(16) unsigned Vs[2][128 * PH];
    __shared__ __align__(16) unsigned Ps[2][128 * PH];
    __shared__ float lsm[128];

    const int z = blockIdx.z;
    const __half* vmat = z ? v2 : v1;
    const __half* pm  = z ? p2 : p1;
    const float* xq   = z ? xq2 : xq1;
    const float* gmp  = z ? gm2 : gm1;
    const float* ps   = z ? ps2 : ps1;
    float* out = outbase + (size_t)z * CC * NPIX;

    const int tid = threadIdx.x;
    const int lane = tid & 31, wid = tid >> 5;
    const int g = lane >> 2, tig = lane & 3;
    const int m_off = (wid >> 1) * 32;
    const int n_off = (wid & 1) * 64;
    const int m0 = blockIdx.y * 128, n0 = blockIdx.x * 128;

    const int lrowA = lane & 15, lkofA = (lane & 16) ? 4 : 0;
    const int lrowB = lane & 7,  lkofB = (lane & 8) ? 4 : 0;
    const unsigned sV0 = smem_u32(&Vs[0][0]);
    const unsigned sP0 = smem_u32(&Ps[0][0]);

    float acc[2][8][4] = {};

    const int row = tid >> 2, u = tid & 3;

    uint4 rV0, rV1, rP0, rP1;

    #define AV_LOAD(kt) { \
        rV0 = *(const uint4*)&vmat[(size_t)(m0 + row) * NPIX + (kt) + u * 8]; \
        rV1 = *(const uint4*)&vmat[(size_t)(m0 + row + 64) * NPIX + (kt) + u * 8]; \
        rP0 = *(const uint4*)&pm[(size_t)(n0 + row) * NPIX + (kt) + u * 8]; \
        rP1 = *(const uint4*)&pm[(size_t)(n0 + row + 64) * NPIX + (kt) + u * 8]; }

    #define AV_STORE(buf) { \
        *(uint4*)&Vs[buf][row * PH + u * 4] = rV0; \
        *(uint4*)&Vs[buf][(row + 64) * PH + u * 4] = rV1; \
        *(uint4*)&Ps[buf][row * PH + u * 4] = rP0; \
        *(uint4*)&Ps[buf][(row + 64) * PH + u * 4] = rP1; }

    {
        int col = tid >> 1, q = tid & 1;
        const float* pp = ps + (size_t)(n0 + col) * 32 + q * 16;
        float s = 0.f;
        #pragma unroll
        for (int i = 0; i < 16; i++) s += pp[i];
        s += __shfl_xor_sync(0xffffffffu, s, 1);
        if (q == 0) lsm[col] = s;
    }

    AV_LOAD(0);
    AV_STORE(0);
    __syncthreads();

    int buf = 0;
    for (int c = 0; c < NPIX / 32; c++) {
        const bool more = (c + 1 < NPIX / 32);
        if (more) { const int ktn = (c + 1) * 32; AV_LOAD(ktn); }

        const unsigned bufoff = buf * 128 * PH * 4;
        #pragma unroll
        for (int ks = 0; ks < 2; ks++) {
            const int k0h = ks * 8;
            unsigned a[2][4], b[8][2];
            #pragma unroll
            for (int mf = 0; mf < 2; mf++) {
                unsigned ro = ((m_off + mf * 16 + lrowA) * PH + k0h + lkofA) * 4;
                ldsm4(a[mf], sV0 + bufoff + ro);
            }
            #pragma unroll
            for (int nf = 0; nf < 8; nf++) {
                unsigned ro = ((n_off + nf * 8 + lrowB) * PH + k0h + lkofB) * 4;
                ldsm2(b[nf], sP0 + bufoff + ro);
            }
            #pragma unroll
            for (int mf = 0; mf < 2; mf++)
                #pragma unroll
                for (int nf = 0; nf < 8; nf++)
                    mma16h(acc[mf][nf], a[mf], b[nf]);
        }
        if (more) AV_STORE(buf ^ 1);
        __syncthreads();
        buf ^= 1;
    }

    const float gm = gmp[0];
    #pragma unroll
    for (int mf = 0; mf < 2; mf++) {
        int r0 = m0 + m_off + mf * 16 + g;
        int r1 = r0 + 8;
        #pragma unroll
        for (int nf = 0; nf < 8; nf++) {
            int lcol = n_off + nf * 8 + 2 * tig;
            int col = n0 + lcol;
            float sa = gm / lsm[lcol];
            float sb = gm / lsm[lcol + 1];
            float2 x0 = *(const float2*)&xq[r0 * NPIX + col];
            float2 x1 = *(const float2*)&xq[r1 * NPIX + col];
            *(float2*)&out[r0 * NPIX + col] =
                make_float2(acc[mf][nf][0] * sa + x0.x, acc[mf][nf][1] * sb + x0.y);
            *(float2*)&out[r1 * NPIX + col] =
                make_float2(acc[mf][nf][2] * sa + x1.x, acc[mf][nf][3] * sb + x1.y);
        }
    }
}

// ---------------------------------------------------------------------------
extern "C" void kernel_launch(void* const* d_in, const int* in_sizes, int n_in,
                              void* d_out, int out_size)
{
    const float* x1    = (const float*)d_in[0];
    const float* x2    = (const float*)d_in[1];
    const float* sx1_w = (const float*)d_in[2];
    const float* sy1_w = (const float*)d_in[3];
    const float* bn1x  = (const float*)d_in[4];
    const float* bn1y  = (const float*)d_in[5];
    const float* sx2_w = (const float*)d_in[6];
    const float* sy2_w = (const float*)d_in[7];
    const float* bn2x  = (const float*)d_in[8];
    const float* bn2y  = (const float*)d_in[9];
    const float* q1_w  = (const float*)d_in[10];
    const float* q1_b  = (const float*)d_in[11];
    const float* k1_w  = (const float*)d_in[12];
    const float* k1_b  = (const float*)d_in[13];
    const float* v1_w  = (const float*)d_in[14];
    const float* v1_b  = (const float*)d_in[15];
    const float* q2_w  = (const float*)d_in[16];
    const float* q2_b  = (const float*)d_in[17];
    const float* k2_w  = (const float*)d_in[18];
    const float* k2_b  = (const float*)d_in[19];
    const float* v2_w  = (const float*)d_in[20];
    const float* v2_b  = (const float*)d_in[21];
    const float* gamma1 = (const float*)d_in[22];
    const float* gamma2 = (const float*)d_in[23];
    float* out = (float*)d_out;

    __half *xt1, *xt2, *xfh1, *xfh2, *qh1, *kh1, *qh2, *kh2, *vh1, *vh2;
    __half *wx1h, *wy1h, *wx2h, *wy2h, *p1, *p2;
    float *ps1, *ps2;
    cudaGetSymbolAddress((void**)&xt1, g_xt1);
    cudaGetSymbolAddress((void**)&xt2, g_xt2);
    cudaGetSymbolAddress((void**)&xfh1, g_xfh1);
    cudaGetSymbolAddress((void**)&xfh2, g_xfh2);
    cudaGetSymbolAddress((void**)&qh1, g_qh1);
    cudaGetSymbolAddress((void**)&kh1, g_kh1);
    cudaGetSymbolAddress((void**)&qh2, g_qh2);
    cudaGetSymbolAddress((void**)&kh2, g_kh2);
    cudaGetSymbolAddress((void**)&vh1, g_vh1);
    cudaGetSymbolAddress((void**)&vh2, g_vh2);
    cudaGetSymbolAddress((void**)&p1, g_p1);
    cudaGetSymbolAddress((void**)&p2, g_p2);
    cudaGetSymbolAddress((void**)&ps1, g_ps1);
    cudaGetSymbolAddress((void**)&ps2, g_ps2);
    cudaGetSymbolAddress((void**)&wx1h, g_wx1h);
    cudaGetSymbolAddress((void**)&wy1h, g_wy1h);
    cudaGetSymbolAddress((void**)&wx2h, g_wx2h);
    cudaGetSymbolAddress((void**)&wy2h, g_wy2h);

    dim3 blk(256);

    prep_kernel<<<9728, blk>>>(sx1_w, sy1_w, sx2_w, sy2_w,
                               wx1h, wy1h, wx2h, wy2h,
                               x1, x2, xt1, xt2);

    sobel_fp16<<<dim3(32, 4, 2), blk>>>(
        xt1, wx1h, wy1h, bn1x, bn1y, xfh1,
        xt2, wx2h, wy2h, bn2x, bn2y, xfh2);

    ProjAll pa;
    pa.A[0] = q1_w;  pa.B[0] = xt1;  pa.bias[0] = q1_b; pa.out[0] = qh1;
    pa.A[1] = k1_w;  pa.B[1] = xfh2; pa.bias[1] = k1_b; pa.out[1] = kh1;
    pa.A[2] = q2_w;  pa.B[2] = xt2;  pa.bias[2] = q2_b; pa.out[2] = qh2;
    pa.A[3] = k2_w;  pa.B[3] = xfh1; pa.bias[3] = k2_b; pa.out[3] = kh2;
    pa.A[4] = v1_w;  pa.B[4] = xfh2; pa.bias[4] = v1_b; pa.out[4] = vh1;
    pa.A[5] = v2_w;  pa.B[5] = xfh1; pa.bias[5] = v2_b; pa.out[5] = vh2;
    proj_all<<<dim3(32, 12), blk>>>(pa);

    energy_exp<<<dim3(32, 64, 2), blk>>>(qh1, kh1, p1, ps1,
                                         qh2, kh2, p2, ps2);
    av_fp16<<<dim3(32, 2, 2), blk>>>(vh1, p1, x1, gamma1, ps1,
                                     vh2, p2, x2, gamma2, ps2, out);
}

// round 15
// speedup vs baseline: 1.0036x; 1.0036x over previous
#include <cuda_runtime.h>
#include <cuda_fp16.h>
#include <math.h>

#define CC   256
#define CQ   32
#define NPIX 4096
#define EPSB 1e-5f
#define KW   2304
#define ESH  8.0f

#define PH 20              // half2 tile pad (16B-aligned rows, LDSM conflict-free)
#define PT2 68             // energy staging row stride (u32)

// ---------------- scratch ----------------
__device__ __align__(16) __half g_xt1[NPIX * CC];
__device__ __align__(16) __half g_xt2[NPIX * CC];
__device__ __align__(16) __half g_xfh1[NPIX * CC];
__device__ __align__(16) __half g_xfh2[NPIX * CC];
__device__ __align__(16) __half g_qh1[NPIX * CQ];
__device__ __align__(16) __half g_kh1[NPIX * CQ];
__device__ __align__(16) __half g_qh2[NPIX * CQ];
__device__ __align__(16) __half g_kh2[NPIX * CQ];
__device__ __align__(16) __half g_vh1[CC * NPIX];
__device__ __align__(16) __half g_vh2[CC * NPIX];
__device__ __align__(16) __half g_p1[(size_t)NPIX * NPIX];
__device__ __align__(16) __half g_p2[(size_t)NPIX * NPIX];
__device__ float g_ps1[NPIX * 32];
__device__ float g_ps2[NPIX * 32];
__device__ __align__(16) float g_avp[4ull * CC * NPIX];   // [z*2+ks][c][n] partials
__device__ __align__(16) __half g_wx1h[CC * KW];
__device__ __align__(16) __half g_wy1h[CC * KW];
__device__ __align__(16) __half g_wx2h[CC * KW];
__device__ __align__(16) __half g_wy2h[CC * KW];

// ---------------- helpers ----------------
__device__ __forceinline__ void mma16h(float* c, const unsigned* a, const unsigned* b) {
    asm volatile(
        "mma.sync.aligned.m16n8k16.row.col.f32.f16.f16.f32 "
        "{%0,%1,%2,%3}, {%4,%5,%6,%7}, {%8,%9}, {%0,%1,%2,%3};"
        : "+f"(c[0]), "+f"(c[1]), "+f"(c[2]), "+f"(c[3])
        : "r"(a[0]), "r"(a[1]), "r"(a[2]), "r"(a[3]), "r"(b[0]), "r"(b[1]));
}
__device__ __forceinline__ unsigned h2u(float lo, float hi) {
    __half2 h = __floats2half2_rn(lo, hi);
    return *reinterpret_cast<unsigned*>(&h);
}
__device__ __forceinline__ void ldsm4(unsigned* r, unsigned addr) {
    asm volatile("ldmatrix.sync.aligned.m8n8.x4.shared.b16 {%0,%1,%2,%3}, [%4];"
                 : "=r"(r[0]), "=r"(r[1]), "=r"(r[2]), "=r"(r[3]) : "r"(addr));
}
__device__ __forceinline__ void ldsm2(unsigned* r, unsigned addr) {
    asm volatile("ldmatrix.sync.aligned.m8n8.x2.shared.b16 {%0,%1}, [%2];"
                 : "=r"(r[0]), "=r"(r[1]) : "r"(addr));
}
__device__ __forceinline__ unsigned smem_u32(const void* p) {
    return (unsigned)__cvta_generic_to_shared(p);
}

// ---------------------------------------------------------------------------
// prep: conv-weight pack + x transpose
// ---------------------------------------------------------------------------
__global__ void prep_kernel(const float* __restrict__ s0, const float* __restrict__ s1,
                            const float* __restrict__ s2, const float* __restrict__ s3,
                            __half* __restrict__ d0, __half* __restrict__ d1,
                            __half* __restrict__ d2, __half* __restrict__ d3,
                            const float* __restrict__ x1, const float* __restrict__ x2,
                            __half* __restrict__ xo1, __half* __restrict__ xo2)
{
    const int bid = blockIdx.x;
    const int tid = threadIdx.x;
    if (bid < 9216) {
        const int y = bid / 2304, xb = bid % 2304;
        const float* s = (y == 0) ? s0 : (y == 1) ? s1 : (y == 2) ? s2 : s3;
        __half* d = (y == 0) ? d0 : (y == 1) ? d1 : (y == 2) ? d2 : d3;
        int t = xb * 256 + tid;
        int m = t / KW, r = t % KW;
        d[t] = __float2half(s[m * KW + (r & 255) * 9 + (r >> 8)]);
    } else {
        __shared__ __align__(16) __half T[64 * 72];
        const int idx = bid - 9216;
        const int z = idx >> 8;
        const int cy = (idx >> 6) & 3;
        const int xb = idx & 63;
        const float* x = z ? x2 : x1;
        __half* o = z ? xo2 : xo1;
        const int c0 = cy * 64, p0 = xb * 64;
        #pragma unroll
        for (int it = 0; it < 16; it++) {
            int i2 = tid + it * 256;
            int c = i2 >> 6, p = i2 & 63;
            T[p * 72 + c] = __float2half(x[(c0 + c) * NPIX + p0 + p]);
        }
        __syncthreads();
        #pragma unroll
        for (int k = 0; k < 2; k++) {
            int i2 = tid + k * 256;
            int p = i2 >> 3, u = i2 & 7;
            *(uint4*)&o[(size_t)(p0 + p) * CC + c0 + u * 8] = *(uint4*)&T[p * 72 + u * 8];
        }
    }
}

// ---------------------------------------------------------------------------
// Sobel fp16 (batched z=2) — unchanged.
// ---------------------------------------------------------------------------
__global__ void __launch_bounds__(256, 2) sobel_fp16(
    const __half* __restrict__ xt1, const __half* __restrict__ wx1,
    const __half* __restrict__ wy1, const float* __restrict__ bn1x,
    const float* __restrict__ bn1y, __half* __restrict__ o1,
    const __half* __restrict__ xt2, const __half* __restrict__ wx2,
    const __half* __restrict__ wy2, const float* __restrict__ bn2x,
    const float* __restrict__ bn2y, __half* __restrict__ o2)
{
    __shared__ __align__(16) unsigned Ax[2][64 * PH];
    __shared__ __align__(16) unsigned Ay[2][64 * PH];
    __shared__ __align__(16) unsigned Bt[2][128 * PH];

    const int z = blockIdx.z;
    const __half* xt  = z ? xt2 : xt1;
    const __half* wxh = z ? wx2 : wx1;
    const __half* wyh = z ? wy2 : wy1;
    const float* bnx = z ? bn2x : bn1x;
    const float* bny = z ? bn2y : bn1y;
    __half* out = z ? o2 : o1;

    const int tid = threadIdx.x;
    const int lane = tid & 31, wid = tid >> 5;
    const int g = lane >> 2, tig = lane & 3;
    const int m_off = (wid >> 2) * 32, n_off = (wid & 3) * 32;
    const int m0 = blockIdx.y * 64, n0 = blockIdx.x * 128;

    const int lrowA = lane & 15, lkofA = (lane & 16) ? 4 : 0;
    const int lrowB = lane & 7,  lkofB = (lane & 8) ? 4 : 0;
    const unsigned sAx0 = smem_u32(&Ax[0][0]);
    const unsigned sAy0 = smem_u32(&Ay[0][0]);
    const unsigned sBt0 = smem_u32(&Bt[0][0]);

    float accx[2][4][4] = {};
    float accy[2][4][4] = {};

    const int am = tid >> 2, ak = tid & 3;
    const int bn = tid & 127, khb = (tid >> 7) * 8;
    const int pix = n0 + bn;
    const int py = pix >> 6, px = pix & 63;

    uint4 rAx, rAy, rB0, rB1;

    #define SB_LOAD(kt) { \
        rAx = *(const uint4*)&wxh[(m0 + am) * KW + (kt) + ak * 8]; \
        rAy = *(const uint4*)&wyh[(m0 + am) * KW + (kt) + ak * 8]; \
        const int tap = (kt) >> 8; \
        const int dy = tap / 3 - 1, dx = tap % 3 - 1; \
        const int cibase = (kt) & 255; \
        const int yy = py + dy, xx = px + dx; \
        if (yy >= 0 && yy < 64 && xx >= 0 && xx < 64) { \
            const __half* sp = xt + (size_t)(yy * 64 + xx) * CC + cibase + khb * 2; \
            rB0 = *(const uint4*)&sp[0]; \
            rB1 = *(const uint4*)&sp[8]; \
        } else { \
            rB0 = make_uint4(0u, 0u, 0u, 0u); \
            rB1 = make_uint4(0u, 0u, 0u, 0u); \
        } }

    #define SB_STORE(buf) { \
        *(uint4*)&Ax[buf][am * PH + ak * 4] = rAx; \
        *(uint4*)&Ay[buf][am * PH + ak * 4] = rAy; \
        *(uint4*)&Bt[buf][bn * PH + khb] = rB0; \
        *(uint4*)&Bt[buf][bn * PH + khb + 4] = rB1; }

    SB_LOAD(0);
    SB_STORE(0);
    __syncthreads();

    int buf = 0;
    for (int c = 0; c < KW / 32; c++) {
        const bool more = (c + 1 < KW / 32);
        if (more) { const int ktn = (c + 1) * 32; SB_LOAD(ktn); }

        const unsigned bufoff = buf * 64 * PH * 4;
        const unsigned bufoffB = buf * 128 * PH * 4;
        #pragma unroll
        for (int ks = 0; ks < 2; ks++) {
            const int k0h = ks * 8;
            unsigned ax[2][4], ay[2][4], b[4][2];
            #pragma unroll
            for (int mf = 0; mf < 2; mf++) {
                unsigned ro = ((m_off + mf * 16 + lrowA) * PH + k0h + lkofA) * 4;
                ldsm4(ax[mf], sAx0 + bufoff + ro);
                ldsm4(ay[mf], sAy0 + bufoff + ro);
            }
            #pragma unroll
            for (int nf = 0; nf < 4; nf++) {
                unsigned ro = ((n_off + nf * 8 + lrowB) * PH + k0h + lkofB) * 4;
                ldsm2(b[nf], sBt0 + bufoffB + ro);
            }
            #pragma unroll
            for (int mf = 0; mf < 2; mf++)
                #pragma unroll
                for (int nf = 0; nf < 4; nf++) {
                    mma16h(accx[mf][nf], ax[mf], b[nf]);
                    mma16h(accy[mf][nf], ay[mf], b[nf]);
                }
        }
        if (more) SB_STORE(buf ^ 1);
        __syncthreads();
        buf ^= 1;
    }

    __half* T = (__half*)&Bt[0][0];
    #pragma unroll
    for (int mf = 0; mf < 2; mf++) {
        int ch0 = m_off + mf * 16 + g;
        int ch1 = ch0 + 8;
        int r0 = m0 + ch0, r1 = m0 + ch1;
        float ivx0 = bnx[r0] * rsqrtf(bnx[768 + r0] + EPSB);
        float ivx1 = bnx[r1] * rsqrtf(bnx[768 + r1] + EPSB);
        float bx0 = bnx[256 + r0], bx1 = bnx[256 + r1];
        float mx0 = bnx[512 + r0], mx1 = bnx[512 + r1];
        float ivy0 = bny[r0] * rsqrtf(bny[768 + r0] + EPSB);
        float ivy1 = bny[r1] * rsqrtf(bny[768 + r1] + EPSB);
        float by0 = bny[256 + r0], by1 = bny[256 + r1];
        float my0 = bny[512 + r0], my1 = bny[512 + r1];
        #pragma unroll
        for (int nf = 0; nf < 4; nf++) {
            int col = n_off + nf * 8 + 2 * tig;
            float gx, gy;
            gx = (accx[mf][nf][0] - mx0) * ivx0 + bx0;
            gy = (accy[mf][nf][0] - my0) * ivy0 + by0;
            T[col * 72 + ch0] = __float2half(sqrtf(gx * gx + gy * gy));
            gx = (accx[mf][nf][1] - mx0) * ivx0 + bx0;
            gy = (accy[mf][nf][1] - my0) * ivy0 + by0;
            T[(col + 1) * 72 + ch0] = __float2half(sqrtf(gx * gx + gy * gy));
            gx = (accx[mf][nf][2] - mx1) * ivx1 + bx1;
            gy = (accy[mf][nf][2] - my1) * ivy1 + by1;
            T[col * 72 + ch1] = __float2half(sqrtf(gx * gx + gy * gy));
            gx = (accx[mf][nf][3] - mx1) * ivx1 + bx1;
            gy = (accy[mf][nf][3] - my1) * ivy1 + by1;
            T[(col + 1) * 72 + ch1] = __float2half(sqrtf(gx * gx + gy * gy));
        }
    }
    __syncthreads();
    #pragma unroll
    for (int k = 0; k < 4; k++) {
        int idx = tid + k * 256;
        int p = idx >> 3, u = idx & 7;
        *(uint4*)&out[(size_t)(n0 + p) * CC + m0 + u * 8] = *(uint4*)&T[p * 72 + u * 8];
    }
}

// ---------------------------------------------------------------------------
// proj merged (6 GEMMs): grid (32, 12) — unchanged.
// ---------------------------------------------------------------------------
struct ProjAll {
    const float* A[6];
    const __half* B[6];
    const float* bias[6];
    __half* out[6];
};

__global__ void __launch_bounds__(256, 2) proj_all(ProjAll args)
{
    __shared__ __align__(16) unsigned As[2][64 * PH];
    __shared__ __align__(16) unsigned Bt[2][128 * PH];

    const int yb = blockIdx.y;
    const int zi = (yb < 4) ? yb : 4 + ((yb - 4) >> 2);
    const int my = (yb < 4) ? 0 : ((yb - 4) & 3);
    const int M = (yb < 4) ? CQ : CC;
    const float* A = args.A[zi];
    const __half* B = args.B[zi];
    const float* bias = args.bias[zi];
    __half* out = args.out[zi];

    const int tid = threadIdx.x;
    const int lane = tid & 31, wid = tid >> 5;
    const int g = lane >> 2, tig = lane & 3;
    const int m_off = (wid >> 2) * 32, n_off = (wid & 3) * 32;
    const int m0 = my * 64, n0 = blockIdx.x * 128;

    const int lrowA = lane & 15, lkofA = (lane & 16) ? 4 : 0;
    const int lrowB = lane & 7,  lkofB = (lane & 8) ? 4 : 0;
    const unsigned sAs0 = smem_u32(&As[0][0]);
    const unsigned sBt0 = smem_u32(&Bt[0][0]);

    float acc[2][4][4] = {};

    const int am = tid >> 2, ak = tid & 3;
    const int brow = tid >> 2, bu = tid & 3;

    unsigned rA[4];
    uint4 rB0, rB1;

    #define PJ_LOAD(kt) { \
        if (m0 + am < M) { \
            float4 a0 = *(const float4*)&A[(m0 + am) * 256 + (kt) + ak * 8]; \
            float4 a1 = *(const float4*)&A[(m0 + am) * 256 + (kt) + ak * 8 + 4]; \
            rA[0] = h2u(a0.x, a0.y); rA[1] = h2u(a0.z, a0.w); \
            rA[2] = h2u(a1.x, a1.y); rA[3] = h2u(a1.z, a1.w); \
        } else { rA[0] = rA[1] = rA[2] = rA[3] = 0u; } \
        rB0 = *(const uint4*)&B[(size_t)(n0 + brow) * CC + (kt) + bu * 8]; \
        rB1 = *(const uint4*)&B[(size_t)(n0 + brow + 64) * CC + (kt) + bu * 8]; }

    #define PJ_STORE(buf) { \
        *(uint4*)&As[buf][am * PH + ak * 4] = make_uint4(rA[0], rA[1], rA[2], rA[3]); \
        *(uint4*)&Bt[buf][brow * PH + bu * 4] = rB0; \
        *(uint4*)&Bt[buf][(brow + 64) * PH + bu * 4] = rB1; }

    PJ_LOAD(0);
    PJ_STORE(0);
    __syncthreads();

    int buf = 0;
    for (int c = 0; c < 8; c++) {
        const bool more = (c + 1 < 8);
        if (more) { const int ktn = (c + 1) * 32; PJ_LOAD(ktn); }

        const unsigned bufoff = buf * 64 * PH * 4;
        const unsigned bufoffB = buf * 128 * PH * 4;
        #pragma unroll
        for (int ks = 0; ks < 2; ks++) {
            const int k0h = ks * 8;
            unsigned a[2][4], b[4][2];
            #pragma unroll
            for (int mf = 0; mf < 2; mf++) {
                unsigned ro = ((m_off + mf * 16 + lrowA) * PH + k0h + lkofA) * 4;
                ldsm4(a[mf], sAs0 + bufoff + ro);
            }
            #pragma unroll
            for (int nf = 0; nf < 4; nf++) {
                unsigned ro = ((n_off + nf * 8 + lrowB) * PH + k0h + lkofB) * 4;
                ldsm2(b[nf], sBt0 + bufoffB + ro);
            }
            #pragma unroll
            for (int mf = 0; mf < 2; mf++)
                #pragma unroll
                for (int nf = 0; nf < 4; nf++)
                    mma16h(acc[mf][nf], a[mf], b[nf]);
        }
        if (more) PJ_STORE(buf ^ 1);
        __syncthreads();
        buf ^= 1;
    }

    if (M == CQ) {
        #pragma unroll
        for (int mf = 0; mf < 2; mf++) {
            int r0 = m0 + m_off + mf * 16 + g;
            int r1 = r0 + 8;
            #pragma unroll
            for (int nf = 0; nf < 4; nf++) {
                int col = n0 + n_off + nf * 8 + 2 * tig;
                if (r0 < M) {
                    float b0 = bias[r0];
                    out[(size_t)col * CQ + r0]       = __float2half(acc[mf][nf][0] + b0);
                    out[(size_t)(col + 1) * CQ + r0] = __float2half(acc[mf][nf][1] + b0);
                }
                if (r1 < M) {
                    float b1 = bias[r1];
                    out[(size_t)col * CQ + r1]       = __float2half(acc[mf][nf][2] + b1);
                    out[(size_t)(col + 1) * CQ + r1] = __float2half(acc[mf][nf][3] + b1);
                }
            }
        }
    } else {
        #pragma unroll
        for (int mf = 0; mf < 2; mf++) {
            int r0 = m0 + m_off + mf * 16 + g;
            int r1 = r0 + 8;
            float b0 = bias[r0];
            float b1 = bias[r1];
            #pragma unroll
            for (int nf = 0; nf < 4; nf++) {
                int col = n0 + n_off + nf * 8 + 2 * tig;
                *(unsigned*)&out[(size_t)r0 * NPIX + col] =
                    h2u(acc[mf][nf][0] + b0, acc[mf][nf][1] + b0);
                *(unsigned*)&out[(size_t)r1 * NPIX + col] =
                    h2u(acc[mf][nf][2] + b1, acc[mf][nf][3] + b1);
            }
        }
    }
}

// ---------------------------------------------------------------------------
// energy+exp (batched z=2) — coalesced staging version (working).
// ---------------------------------------------------------------------------
__global__ void energy_exp(const __half* __restrict__ q1, const __half* __restrict__ k1,
                           __half* __restrict__ p1, float* __restrict__ ps1,
                           const __half* __restrict__ q2, const __half* __restrict__ k2,
                           __half* __restrict__ p2, float* __restrict__ ps2)
{
    __shared__ __align__(16) unsigned Qh[64 * PH];
    __shared__ __align__(16) unsigned Kh[128 * PH];
    __shared__ __align__(16) unsigned Pt[64 * PT2];
    __shared__ float rsum[64][4];

    const int z = blockIdx.z;
    const __half* q = z ? q2 : q1;
    const __half* k = z ? k2 : k1;
    __half* pm = z ? p2 : p1;
    float* ps = z ? ps2 : ps1;

    const int tid = threadIdx.x;
    const int lane = tid & 31, wid = tid >> 5;
    const int g = lane >> 2, tig = lane & 3;
    const int m_off = (wid >> 2) * 32, n_off = (wid & 3) * 32;
    const int kc = wid & 3;
    const int m0 = blockIdx.y * 64, n0 = blockIdx.x * 128;

    const int lrowA = lane & 15, lkofA = (lane & 16) ? 4 : 0;
    const int lrowB = lane & 7,  lkofB = (lane & 8) ? 4 : 0;
    const unsigned sQ = smem_u32(&Qh[0]);
    const unsigned sK = smem_u32(&Kh[0]);

    {
        int m = tid >> 2, u = tid & 3;
        *(uint4*)&Qh[m * PH + u * 4] = *(const uint4*)&q[(size_t)(m0 + m) * CQ + u * 8];
    }
    #pragma unroll
    for (int kk = 0; kk < 2; kk++) {
        int idx = tid + kk * 256;
        int n = idx >> 2, u = idx & 3;
        *(uint4*)&Kh[n * PH + u * 4] = *(const uint4*)&k[(size_t)(n0 + n) * CQ + u * 8];
    }
    __syncthreads();

    float acc[2][4][4] = {};
    #pragma unroll
    for (int ks = 0; ks < 2; ks++) {
        const int k0h = ks * 8;
        unsigned a[2][4], b[4][2];
        #pragma unroll
        for (int mf = 0; mf < 2; mf++) {
            unsigned ro = ((m_off + mf * 16 + lrowA) * PH + k0h + lkofA) * 4;
            ldsm4(a[mf], sQ + ro);
        }
        #pragma unroll
        for (int nf = 0; nf < 4; nf++) {
            unsigned ro = ((n_off + nf * 8 + lrowB) * PH + k0h + lkofB) * 4;
            ldsm2(b[nf], sK + ro);
        }
        #pragma unroll
        for (int mf = 0; mf < 2; mf++)
            #pragma unroll
            for (int nf = 0; nf < 4; nf++)
                mma16h(acc[mf][nf], a[mf], b[nf]);
    }

    float s[2][2] = {};
    #pragma unroll
    for (int mf = 0; mf < 2; mf++) {
        int lr0 = m_off + mf * 16 + g;
        int lr1 = lr0 + 8;
        #pragma unroll
        for (int nf = 0; nf < 4; nf++) {
            int cu = (n_off >> 1) + nf * 4 + tig;
            float p0 = __expf(acc[mf][nf][0] - ESH);
            float p1 = __expf(acc[mf][nf][1] - ESH);
            float p2 = __expf(acc[mf][nf][2] - ESH);
            float p3 = __expf(acc[mf][nf][3] - ESH);
            s[mf][0] += p0 + p1;
            s[mf][1] += p2 + p3;
            Pt[lr0 * PT2 + cu] = h2u(p0, p1);
            Pt[lr1 * PT2 + cu] = h2u(p2, p3);
        }
    }
    #pragma unroll
    for (int mf = 0; mf < 2; mf++) {
        #pragma unroll
        for (int j = 0; j < 2; j++) {
            s[mf][j] += __shfl_xor_sync(0xffffffffu, s[mf][j], 1);
            s[mf][j] += __shfl_xor_sync(0xffffffffu, s[mf][j], 2);
        }
    }
    if (tig == 0) {
        #pragma unroll
        for (int mf = 0; mf < 2; mf++) {
            int lr0 = m_off + mf * 16 + g;
            rsum[lr0][kc] = s[mf][0];
            rsum[lr0 + 8][kc] = s[mf][1];
        }
    }
    __syncthreads();

    #pragma unroll
    for (int kk = 0; kk < 4; kk++) {
        int idx = tid + kk * 256;
        int r = idx >> 4, u = idx & 15;
        *(uint4*)&pm[(size_t)(m0 + r) * NPIX + n0 + u * 8] = *(uint4*)&Pt[r * PT2 + u * 4];
    }
    if (tid < 64) {
        ps[(size_t)(m0 + tid) * 32 + blockIdx.x] =
            rsum[tid][0] + rsum[tid][1] + rsum[tid][2] + rsum[tid][3];
    }
}

// ---------------------------------------------------------------------------
// av split-K (batched z=2): partial[m][n] = sum_{k in half} V[m][k] P'[n][k]
// m-tile 128, n-tile 128, K half = 2048. grid (32, 4, 2): y = mt*2 + ks.
// Writes raw fp32 partials; av_fin folds, scales, adds residual.
// ---------------------------------------------------------------------------
__global__ void __launch_bounds__(256, 2) av_fp16(
    const __half* __restrict__ v1, const __half* __restrict__ p1,
    const __half* __restrict__ v2, const __half* __restrict__ p2,
    float* __restrict__ pav)
{
    __shared__ __align__(16) unsigned Vs[2][128 * PH];
    __shared__ __align__(16) unsigned Ps[2][128 * PH];

    const int z = blockIdx.z;
    const int mt = blockIdx.y >> 1;
    const int ksl = blockIdx.y & 1;
    const __half* vmat = z ? v2 : v1;
    const __half* pm  = z ? p2 : p1;
    float* po = pav + (size_t)(z * 2 + ksl) * CC * NPIX;

    const int tid = threadIdx.x;
    const int lane = tid & 31, wid = tid >> 5;
    const int g = lane >> 2, tig = lane & 3;
    const int m_off = (wid >> 1) * 32;
    const int n_off = (wid & 1) * 64;
    const int m0 = mt * 128, n0 = blockIdx.x * 128;
    const int kbase = ksl * (NPIX / 2);

    const int lrowA = lane & 15, lkofA = (lane & 16) ? 4 : 0;
    const int lrowB = lane & 7,  lkofB = (lane & 8) ? 4 : 0;
    const unsigned sV0 = smem_u32(&Vs[0][0]);
    const unsigned sP0 = smem_u32(&Ps[0][0]);

    float acc[2][8][4] = {};

    const int row = tid >> 2, u = tid & 3;

    uint4 rV0, rV1, rP0, rP1;

    #define AV_LOAD(kt) { \
        rV0 = *(const uint4*)&vmat[(size_t)(m0 + row) * NPIX + (kt) + u * 8]; \
        rV1 = *(const uint4*)&vmat[(size_t)(m0 + row + 64) * NPIX + (kt) + u * 8]; \
        rP0 = *(const uint4*)&pm[(size_t)(n0 + row) * NPIX + (kt) + u * 8]; \
        rP1 = *(const uint4*)&pm[(size_t)(n0 + row + 64) * NPIX + (kt) + u * 8]; }

    #define AV_STORE(buf) { \
        *(uint4*)&Vs[buf][row * PH + u * 4] = rV0; \
        *(uint4*)&Vs[buf][(row + 64) * PH + u * 4] = rV1; \
        *(uint4*)&Ps[buf][row * PH + u * 4] = rP0; \
        *(uint4*)&Ps[buf][(row + 64) * PH + u * 4] = rP1; }

    AV_LOAD(kbase);
    AV_STORE(0);
    __syncthreads();

    int buf = 0;
    for (int c = 0; c < NPIX / 64; c++) {
        const bool more = (c + 1 < NPIX / 64);
        if (more) { const int ktn = kbase + (c + 1) * 32; AV_LOAD(ktn); }

        const unsigned bufoff = buf * 128 * PH * 4;
        #pragma unroll
        for (int ks = 0; ks < 2; ks++) {
            const int k0h = ks * 8;
            unsigned a[2][4], b[8][2];
            #pragma unroll
            for (int mf = 0; mf < 2; mf++) {
                unsigned ro = ((m_off + mf * 16 + lrowA) * PH + k0h + lkofA) * 4;
                ldsm4(a[mf], sV0 + bufoff + ro);
            }
            #pragma unroll
            for (int nf = 0; nf < 8; nf++) {
                unsigned ro = ((n_off + nf * 8 + lrowB) * PH + k0h + lkofB) * 4;
                ldsm2(b[nf], sP0 + bufoff + ro);
            }
            #pragma unroll
            for (int mf = 0; mf < 2; mf++)
                #pragma unroll
                for (int nf = 0; nf < 8; nf++)
                    mma16h(acc[mf][nf], a[mf], b[nf]);
        }
        if (more) AV_STORE(buf ^ 1);
        __syncthreads();
        buf ^= 1;
    }

    #pragma unroll
    for (int mf = 0; mf < 2; mf++) {
        int r0 = m0 + m_off + mf * 16 + g;
        int r1 = r0 + 8;
        #pragma unroll
        for (int nf = 0; nf < 8; nf++) {
            int col = n0 + n_off + nf * 8 + 2 * tig;
            *(float2*)&po[(size_t)r0 * NPIX + col] =
                make_float2(acc[mf][nf][0], acc[mf][nf][1]);
            *(float2*)&po[(size_t)r1 * NPIX + col] =
                make_float2(acc[mf][nf][2], acc[mf][nf][3]);
        }
    }
}

// ---------------------------------------------------------------------------
// av_fin: out[c][n] = gm/l[n] * (p0+p1)[c][n] + xq[c][n].
// grid (64, 2), block 256. l computed from ps partials in prologue.
// ---------------------------------------------------------------------------
__global__ void av_fin(const float* __restrict__ pav,
                       const float* __restrict__ ps1, const float* __restrict__ ps2,
                       const float* __restrict__ x1, const float* __restrict__ x2,
                       const float* __restrict__ gm1, const float* __restrict__ gm2,
                       float* __restrict__ outbase)
{
    __shared__ float lsm[64];
    const int z = blockIdx.y;
    const int n0 = blockIdx.x * 64;
    const float* ps = z ? ps2 : ps1;
    const float* xq = z ? x2 : x1;
    const float gm  = z ? gm2[0] : gm1[0];
    const float* pa = pav + (size_t)(z * 2) * CC * NPIX;
    const float* pb = pav + (size_t)(z * 2 + 1) * CC * NPIX;
    float* out = outbase + (size_t)z * CC * NPIX;

    const int tid = threadIdx.x;
    {
        int col = tid >> 2, q = tid & 3;
        const float* pp = ps + (size_t)(n0 + col) * 32 + q * 8;
        float s = 0.f;
        #pragma unroll
        for (int i = 0; i < 8; i++) s += pp[i];
        s += __shfl_xor_sync(0xffffffffu, s, 1);
        s += __shfl_xor_sync(0xffffffffu, s, 2);
        if (q == 0) lsm[col] = s;
    }
    __syncthreads();

    const int c4 = (tid & 15) * 4;
    const int r0 = tid >> 4;
    float4 li;
    li.x = gm / lsm[c4];
    li.y = gm / lsm[c4 + 1];
    li.z = gm / lsm[c4 + 2];
    li.w = gm / lsm[c4 + 3];

    for (int r = r0; r < CC; r += 16) {
        size_t off = (size_t)r * NPIX + n0 + c4;
        float4 a = *(const float4*)&pa[off];
        float4 b = *(const float4*)&pb[off];
        float4 xv = *(const float4*)&xq[off];
        float4 ov;
        ov.x = (a.x + b.x) * li.x + xv.x;
        ov.y = (a.y + b.y) * li.y + xv.y;
        ov.z = (a.z + b.z) * li.z + xv.z;
        ov.w = (a.w + b.w) * li.w + xv.w;
        *(float4*)&out[off] = ov;
    }
}

// ---------------------------------------------------------------------------
extern "C" void kernel_launch(void* const* d_in, const int* in_sizes, int n_in,
                              void* d_out, int out_size)
{
    const float* x1    = (const float*)d_in[0];
    const float* x2    = (const float*)d_in[1];
    const float* sx1_w = (const float*)d_in[2];
    const float* sy1_w = (const float*)d_in[3];
    const float* bn1x  = (const float*)d_in[4];
    const float* bn1y  = (const float*)d_in[5];
    const float* sx2_w = (const float*)d_in[6];
    const float* sy2_w = (const float*)d_in[7];
    const float* bn2x  = (const float*)d_in[8];
    const float* bn2y  = (const float*)d_in[9];
    const float* q1_w  = (const float*)d_in[10];
    const float* q1_b  = (const float*)d_in[11];
    const float* k1_w  = (const float*)d_in[12];
    const float* k1_b  = (const float*)d_in[13];
    const float* v1_w  = (const float*)d_in[14];
    const float* v1_b  = (const float*)d_in[15];
    const float* q2_w  = (const float*)d_in[16];
    const float* q2_b  = (const float*)d_in[17];
    const float* k2_w  = (const float*)d_in[18];
    const float* k2_b  = (const float*)d_in[19];
    const float* v2_w  = (const float*)d_in[20];
    const float* v2_b  = (const float*)d_in[21];
    const float* gamma1 = (const float*)d_in[22];
    const float* gamma2 = (const float*)d_in[23];
    float* out = (float*)d_out;

    __half *xt1, *xt2, *xfh1, *xfh2, *qh1, *kh1, *qh2, *kh2, *vh1, *vh2;
    __half *wx1h, *wy1h, *wx2h, *wy2h, *p1, *p2;
    float *ps1, *ps2, *pav;
    cudaGetSymbolAddress((void**)&xt1, g_xt1);
    cudaGetSymbolAddress((void**)&xt2, g_xt2);
    cudaGetSymbolAddress((void**)&xfh1, g_xfh1);
    cudaGetSymbolAddress((void**)&xfh2, g_xfh2);
    cudaGetSymbolAddress((void**)&qh1, g_qh1);
    cudaGetSymbolAddress((void**)&kh1, g_kh1);
    cudaGetSymbolAddress((void**)&qh2, g_qh2);
    cudaGetSymbolAddress((void**)&kh2, g_kh2);
    cudaGetSymbolAddress((void**)&vh1, g_vh1);
    cudaGetSymbolAddress((void**)&vh2, g_vh2);
    cudaGetSymbolAddress((void**)&p1, g_p1);
    cudaGetSymbolAddress((void**)&p2, g_p2);
    cudaGetSymbolAddress((void**)&ps1, g_ps1);
    cudaGetSymbolAddress((void**)&ps2, g_ps2);
    cudaGetSymbolAddress((void**)&pav, g_avp);
    cudaGetSymbolAddress((void**)&wx1h, g_wx1h);
    cudaGetSymbolAddress((void**)&wy1h, g_wy1h);
    cudaGetSymbolAddress((void**)&wx2h, g_wx2h);
    cudaGetSymbolAddress((void**)&wy2h, g_wy2h);

    dim3 blk(256);

    prep_kernel<<<9728, blk>>>(sx1_w, sy1_w, sx2_w, sy2_w,
                               wx1h, wy1h, wx2h, wy2h,
                               x1, x2, xt1, xt2);

    sobel_fp16<<<dim3(32, 4, 2), blk>>>(
        xt1, wx1h, wy1h, bn1x, bn1y, xfh1,
        xt2, wx2h, wy2h, bn2x, bn2y, xfh2);

    ProjAll pa;
    pa.A[0] = q1_w;  pa.B[0] = xt1;  pa.bias[0] = q1_b; pa.out[0] = qh1;
    pa.A[1] = k1_w;  pa.B[1] = xfh2; pa.bias[1] = k1_b; pa.out[1] = kh1;
    pa.A[2] = q2_w;  pa.B[2] = xt2;  pa.bias[2] = q2_b; pa.out[2] = qh2;
    pa.A[3] = k2_w;  pa.B[3] = xfh1; pa.bias[3] = k2_b; pa.out[3] = kh2;
    pa.A[4] = v1_w;  pa.B[4] = xfh2; pa.bias[4] = v1_b; pa.out[4] = vh1;
    pa.A[5] = v2_w;  pa.B[5] = xfh1; pa.bias[5] = v2_b; pa.out[5] = vh2;
    proj_all<<<dim3(32, 12), blk>>>(pa);

    energy_exp<<<dim3(32, 64, 2), blk>>>(qh1, kh1, p1, ps1,
                                         qh2, kh2, p2, ps2);
    av_fp16<<<dim3(32, 4, 2), blk>>>(vh1, p1, vh2, p2, pav);
    av_fin<<<dim3(64, 2), blk>>>(pav, ps1, ps2, x1, x2, gamma1, gamma2, out);
}

// round 17
// speedup vs baseline: 1.0692x; 1.0653x over previous
#include <cuda_runtime.h>
#include <cuda_fp16.h>
#include <math.h>

#define CC   256
#define CQ   32
#define NPIX 4096
#define EPSB 1e-5f
#define KW   2304
#define ESH  8.0f

#define PH 20              // half2 tile pad, k-chunk-32 kernels (energy/av)
#define PW 36              // half2 tile pad, k-chunk-64 kernels (sobel/proj)
#define PT2 68             // energy staging row stride (u32)

#define SOBEL_SMEM ((2*64*PW*2 + 2*128*PW) * 4)     // 73728
#define PROJ_SMEM  ((2*64*PW + 2*128*PW) * 4)       // 55296

// ---------------- scratch ----------------
__device__ __align__(16) __half g_xt1[NPIX * CC];
__device__ __align__(16) __half g_xt2[NPIX * CC];
__device__ __align__(16) __half g_xfh1[NPIX * CC];
__device__ __align__(16) __half g_xfh2[NPIX * CC];
__device__ __align__(16) __half g_qh1[NPIX * CQ];
__device__ __align__(16) __half g_kh1[NPIX * CQ];
__device__ __align__(16) __half g_qh2[NPIX * CQ];
__device__ __align__(16) __half g_kh2[NPIX * CQ];
__device__ __align__(16) __half g_vh1[CC * NPIX];
__device__ __align__(16) __half g_vh2[CC * NPIX];
__device__ __align__(16) __half g_p1[(size_t)NPIX * NPIX];
__device__ __align__(16) __half g_p2[(size_t)NPIX * NPIX];
__device__ float g_ps1[NPIX * 32];
__device__ float g_ps2[NPIX * 32];
__device__ __align__(16) __half g_wx1h[CC * KW];
__device__ __align__(16) __half g_wy1h[CC * KW];
__device__ __align__(16) __half g_wx2h[CC * KW];
__device__ __align__(16) __half g_wy2h[CC * KW];

// ---------------- helpers ----------------
__device__ __forceinline__ void mma16h(float* c, const unsigned* a, const unsigned* b) {
    asm volatile(
        "mma.sync.aligned.m16n8k16.row.col.f32.f16.f16.f32 "
        "{%0,%1,%2,%3}, {%4,%5,%6,%7}, {%8,%9}, {%0,%1,%2,%3};"
        : "+f"(c[0]), "+f"(c[1]), "+f"(c[2]), "+f"(c[3])
        : "r"(a[0]), "r"(a[1]), "r"(a[2]), "r"(a[3]), "r"(b[0]), "r"(b[1]));
}
__device__ __forceinline__ unsigned h2u(float lo, float hi) {
    __half2 h = __floats2half2_rn(lo, hi);
    return *reinterpret_cast<unsigned*>(&h);
}
__device__ __forceinline__ void ldsm4(unsigned* r, unsigned addr) {
    asm volatile("ldmatrix.sync.aligned.m8n8.x4.shared.b16 {%0,%1,%2,%3}, [%4];"
                 : "=r"(r[0]), "=r"(r[1]), "=r"(r[2]), "=r"(r[3]) : "r"(addr));
}
__device__ __forceinline__ void ldsm2(unsigned* r, unsigned addr) {
    asm volatile("ldmatrix.sync.aligned.m8n8.x2.shared.b16 {%0,%1}, [%2];"
                 : "=r"(r[0]), "=r"(r[1]) : "r"(addr));
}
__device__ __forceinline__ unsigned smem_u32(const void* p) {
    return (unsigned)__cvta_generic_to_shared(p);
}

// ---------------------------------------------------------------------------
// prep: conv-weight pack + x transpose — unchanged.
// ---------------------------------------------------------------------------
__global__ void prep_kernel(const float* __restrict__ s0, const float* __restrict__ s1,
                            const float* __restrict__ s2, const float* __restrict__ s3,
                            __half* __restrict__ d0, __half* __restrict__ d1,
                            __half* __restrict__ d2, __half* __restrict__ d3,
                            const float* __restrict__ x1, const float* __restrict__ x2,
                            __half* __restrict__ xo1, __half* __restrict__ xo2)
{
    const int bid = blockIdx.x;
    const int tid = threadIdx.x;
    if (bid < 9216) {
        const int y = bid / 2304, xb = bid % 2304;
        const float* s = (y == 0) ? s0 : (y == 1) ? s1 : (y == 2) ? s2 : s3;
        __half* d = (y == 0) ? d0 : (y == 1) ? d1 : (y == 2) ? d2 : d3;
        int t = xb * 256 + tid;
        int m = t / KW, r = t % KW;
        d[t] = __float2half(s[m * KW + (r & 255) * 9 + (r >> 8)]);
    } else {
        __shared__ __align__(16) __half T[64 * 72];
        const int idx = bid - 9216;
        const int z = idx >> 8;
        const int cy = (idx >> 6) & 3;
        const int xb = idx & 63;
        const float* x = z ? x2 : x1;
        __half* o = z ? xo2 : xo1;
        const int c0 = cy * 64, p0 = xb * 64;
        #pragma unroll
        for (int it = 0; it < 16; it++) {
            int i2 = tid + it * 256;
            int c = i2 >> 6, p = i2 & 63;
            T[p * 72 + c] = __float2half(x[(c0 + c) * NPIX + p0 + p]);
        }
        __syncthreads();
        #pragma unroll
        for (int k = 0; k < 2; k++) {
            int i2 = tid + k * 256;
            int p = i2 >> 3, u = i2 & 7;
            *(uint4*)&o[(size_t)(p0 + p) * CC + c0 + u * 8] = *(uint4*)&T[p * 72 + u * 8];
        }
    }
}

// ---------------------------------------------------------------------------
// Sobel fp16 (batched z=2), k-chunk 64 halves (36 chunks), dynamic smem.
// grid (32, 4, 2), block 256 (2x4 warps), m-tile 64 ch, n-tile 128 pix.
// ---------------------------------------------------------------------------
__global__ void __launch_bounds__(256, 2) sobel_fp16(
    const __half* __restrict__ xt1, const __half* __restrict__ wx1,
    const __half* __restrict__ wy1, const float* __restrict__ bn1x,
    const float* __restrict__ bn1y, __half* __restrict__ o1,
    const __half* __restrict__ xt2, const __half* __restrict__ wx2,
    const __half* __restrict__ wy2, const float* __restrict__ bn2x,
    const float* __restrict__ bn2y, __half* __restrict__ o2)
{
    extern __shared__ __align__(16) unsigned sh[];
    unsigned* AxB = sh;                         // 2 * 64*PW
    unsigned* AyB = sh + 2 * 64 * PW;           // 2 * 64*PW
    unsigned* BtB = sh + 4 * 64 * PW;           // 2 * 128*PW

    const int z = blockIdx.z;
    const __half* xt  = z ? xt2 : xt1;
    const __half* wxh = z ? wx2 : wx1;
    const __half* wyh = z ? wy2 : wy1;
    const float* bnx = z ? bn2x : bn1x;
    const float* bny = z ? bn2y : bn1y;
    __half* out = z ? o2 : o1;

    const int tid = threadIdx.x;
    const int lane = tid & 31, wid = tid >> 5;
    const int g = lane >> 2, tig = lane & 3;
    const int m_off = (wid >> 2) * 32, n_off = (wid & 3) * 32;
    const int m0 = blockIdx.y * 64, n0 = blockIdx.x * 128;

    const int lrowA = lane & 15, lkofA = (lane & 16) ? 4 : 0;
    const int lrowB = lane & 7,  lkofB = (lane & 8) ? 4 : 0;
    const unsigned sAx0 = smem_u32(AxB);
    const unsigned sAy0 = smem_u32(AyB);
    const unsigned sBt0 = smem_u32(BtB);

    float accx[2][4][4] = {};
    float accy[2][4][4] = {};

    // A: 64 rows x 8 uint4 (64 halves); 4 threads/row, 2 uint4 each
    const int am = tid >> 2, aj = (tid & 3) * 2;
    // B: 128 rows x 8 uint4; 2 threads/row, 4 uint4 each
    const int brow = tid >> 1, bh = (tid & 1) * 32;     // half offset 0 or 32
    const int pix = n0 + brow;
    const int py = pix >> 6, px = pix & 63;

    uint4 rAx[2], rAy[2], rB[4];

    #define SB_LOAD(kt) { \
        const __half* wxp = &wxh[(m0 + am) * KW + (kt) + aj * 8]; \
        const __half* wyp = &wyh[(m0 + am) * KW + (kt) + aj * 8]; \
        rAx[0] = *(const uint4*)&wxp[0];  rAx[1] = *(const uint4*)&wxp[8]; \
        rAy[0] = *(const uint4*)&wyp[0];  rAy[1] = *(const uint4*)&wyp[8]; \
        const int tap = (kt) >> 8; \
        const int dy = tap / 3 - 1, dx = tap % 3 - 1; \
        const int cib = (kt) & 255; \
        const int yy = py + dy, xx = px + dx; \
        if (yy >= 0 && yy < 64 && xx >= 0 && xx < 64) { \
            const __half* sp = xt + (size_t)(yy * 64 + xx) * CC + cib + bh; \
            rB[0] = *(const uint4*)&sp[0];  rB[1] = *(const uint4*)&sp[8]; \
            rB[2] = *(const uint4*)&sp[16]; rB[3] = *(const uint4*)&sp[24]; \
        } else { \
            rB[0] = rB[1] = rB[2] = rB[3] = make_uint4(0u, 0u, 0u, 0u); \
        } }

    #define SB_STORE(buf) { \
        unsigned* Ax = AxB + (buf) * 64 * PW; \
        unsigned* Ay = AyB + (buf) * 64 * PW; \
        unsigned* Bt = BtB + (buf) * 128 * PW; \
        *(uint4*)&Ax[am * PW + aj * 4]       = rAx[0]; \
        *(uint4*)&Ax[am * PW + aj * 4 + 4]   = rAx[1]; \
        *(uint4*)&Ay[am * PW + aj * 4]       = rAy[0]; \
        *(uint4*)&Ay[am * PW + aj * 4 + 4]   = rAy[1]; \
        unsigned* bp = &Bt[brow * PW + bh / 2]; \
        *(uint4*)&bp[0]  = rB[0]; *(uint4*)&bp[4]  = rB[1]; \
        *(uint4*)&bp[8]  = rB[2]; *(uint4*)&bp[12] = rB[3]; }

    SB_LOAD(0);
    SB_STORE(0);
    __syncthreads();

    int buf = 0;
    for (int c = 0; c < KW / 64; c++) {
        const bool more = (c + 1 < KW / 64);
        if (more) { const int ktn = (c + 1) * 64; SB_LOAD(ktn); }

        const unsigned bufoff = buf * 64 * PW * 4;
        const unsigned bufoffB = buf * 128 * PW * 4;
        #pragma unroll
        for (int ks = 0; ks < 4; ks++) {
            const int k0h = ks * 8;
            unsigned ax[2][4], ay[2][4], b[4][2];
            #pragma unroll
            for (int mf = 0; mf < 2; mf++) {
                unsigned ro = ((m_off + mf * 16 + lrowA) * PW + k0h + lkofA) * 4;
                ldsm4(ax[mf], sAx0 + bufoff + ro);
                ldsm4(ay[mf], sAy0 + bufoff + ro);
            }
            #pragma unroll
            for (int nf = 0; nf < 4; nf++) {
                unsigned ro = ((n_off + nf * 8 + lrowB) * PW + k0h + lkofB) * 4;
                ldsm2(b[nf], sBt0 + bufoffB + ro);
            }
            #pragma unroll
            for (int mf = 0; mf < 2; mf++)
                #pragma unroll
                for (int nf = 0; nf < 4; nf++) {
                    mma16h(accx[mf][nf], ax[mf], b[nf]);
                    mma16h(accy[mf][nf], ay[mf], b[nf]);
                }
        }
        if (more) SB_STORE(buf ^ 1);
        __syncthreads();
        buf ^= 1;
    }

    __half* T = (__half*)BtB;      // 128 x 136 halves = 34816B <= 36864B
    #pragma unroll
    for (int mf = 0; mf < 2; mf++) {
        int ch0 = m_off + mf * 16 + g;
        int ch1 = ch0 + 8;
        int r0 = m0 + ch0, r1 = m0 + ch1;
        float ivx0 = bnx[r0] * rsqrtf(bnx[768 + r0] + EPSB);
        float ivx1 = bnx[r1] * rsqrtf(bnx[768 + r1] + EPSB);
        float bx0 = bnx[256 + r0], bx1 = bnx[256 + r1];
        float mx0 = bnx[512 + r0], mx1 = bnx[512 + r1];
        float ivy0 = bny[r0] * rsqrtf(bny[768 + r0] + EPSB);
        float ivy1 = bny[r1] * rsqrtf(bny[768 + r1] + EPSB);
        float by0 = bny[256 + r0], by1 = bny[256 + r1];
        float my0 = bny[512 + r0], my1 = bny[512 + r1];
        #pragma unroll
        for (int nf = 0; nf < 4; nf++) {
            int col = n_off + nf * 8 + 2 * tig;
            float gx, gy;
            gx = (accx[mf][nf][0] - mx0) * ivx0 + bx0;
            gy = (accy[mf][nf][0] - my0) * ivy0 + by0;
            T[col * 136 + ch0] = __float2half(sqrtf(gx * gx + gy * gy));
            gx = (accx[mf][nf][1] - mx0) * ivx0 + bx0;
            gy = (accy[mf][nf][1] - my0) * ivy0 + by0;
            T[(col + 1) * 136 + ch0] = __float2half(sqrtf(gx * gx + gy * gy));
            gx = (accx[mf][nf][2] - mx1) * ivx1 + bx1;
            gy = (accy[mf][nf][2] - my1) * ivy1 + by1;
            T[col * 136 + ch1] = __float2half(sqrtf(gx * gx + gy * gy));
            gx = (accx[mf][nf][3] - mx1) * ivx1 + bx1;
            gy = (accy[mf][nf][3] - my1) * ivy1 + by1;
            T[(col + 1) * 136 + ch1] = __float2half(sqrtf(gx * gx + gy * gy));
        }
    }
    __syncthreads();
    #pragma unroll
    for (int k = 0; k < 4; k++) {
        int idx = tid + k * 256;
        int p = idx >> 3, u = idx & 7;
        *(uint4*)&out[(size_t)(n0 + p) * CC + m0 + u * 8] = *(uint4*)&T[p * 136 + u * 8];
    }
}

// ---------------------------------------------------------------------------
// proj merged (6 GEMMs): grid (32, 12), k-chunk 64 (4 chunks), dynamic smem.
// ---------------------------------------------------------------------------
struct ProjAll {
    const float* A[6];
    const __half* B[6];
    const float* bias[6];
    __half* out[6];
};

__global__ void __launch_bounds__(256, 2) proj_all(ProjAll args)
{
    extern __shared__ __align__(16) unsigned sh[];
    unsigned* AsB = sh;                         // 2 * 64*PW
    unsigned* BtB = sh + 2 * 64 * PW;           // 2 * 128*PW

    const int yb = blockIdx.y;
    const int zi = (yb < 4) ? yb : 4 + ((yb - 4) >> 2);
    const int my = (yb < 4) ? 0 : ((yb - 4) & 3);
    const int M = (yb < 4) ? CQ : CC;
    const float* A = args.A[zi];
    const __half* B = args.B[zi];
    const float* bias = args.bias[zi];
    __half* out = args.out[zi];

    const int tid = threadIdx.x;
    const int lane = tid & 31, wid = tid >> 5;
    const int g = lane >> 2, tig = lane & 3;
    const int m_off = (wid >> 2) * 32, n_off = (wid & 3) * 32;
    const int m0 = my * 64, n0 = blockIdx.x * 128;

    const int lrowA = lane & 15, lkofA = (lane & 16) ? 4 : 0;
    const int lrowB = lane & 7,  lkofB = (lane & 8) ? 4 : 0;
    const unsigned sAs0 = smem_u32(AsB);
    const unsigned sBt0 = smem_u32(BtB);

    float acc[2][4][4] = {};

    // A: 64 rows x 64 halves; 4 threads/row, 16 halves each
    const int am = tid >> 2, ah = (tid & 3) * 16;
    // B: 128 rows x 8 uint4; 2 threads/row, 4 uint4 each
    const int brow = tid >> 1, bh = (tid & 1) * 32;

    unsigned rA[8];
    uint4 rB[4];

    #define PJ_LOAD(kt) { \
        if (m0 + am < M) { \
            const float* ap = &A[(m0 + am) * 256 + (kt) + ah]; \
            _Pragma("unroll") \
            for (int q = 0; q < 4; q++) { \
                float4 v = *(const float4*)&ap[q * 4]; \
                rA[q * 2]     = h2u(v.x, v.y); \
                rA[q * 2 + 1] = h2u(v.z, v.w); \
            } \
        } else { \
            _Pragma("unroll") \
            for (int q = 0; q < 8; q++) rA[q] = 0u; \
        } \
        const __half* bp = &B[(size_t)(n0 + brow) * CC + (kt) + bh]; \
        rB[0] = *(const uint4*)&bp[0];  rB[1] = *(const uint4*)&bp[8]; \
        rB[2] = *(const uint4*)&bp[16]; rB[3] = *(const uint4*)&bp[24]; }

    #define PJ_STORE(buf) { \
        unsigned* As = AsB + (buf) * 64 * PW; \
        unsigned* Bt = BtB + (buf) * 128 * PW; \
        unsigned* apo = &As[am * PW + ah / 2]; \
        *(uint4*)&apo[0] = make_uint4(rA[0], rA[1], rA[2], rA[3]); \
        *(uint4*)&apo[4] = make_uint4(rA[4], rA[5], rA[6], rA[7]); \
        unsigned* bpo = &Bt[brow * PW + bh / 2]; \
        *(uint4*)&bpo[0]  = rB[0]; *(uint4*)&bpo[4]  = rB[1]; \
        *(uint4*)&bpo[8]  = rB[2]; *(uint4*)&bpo[12] = rB[3]; }

    PJ_LOAD(0);
    PJ_STORE(0);
    __syncthreads();

    int buf = 0;
    for (int c = 0; c < 4; c++) {
        const bool more = (c + 1 < 4);
        if (more) { const int ktn = (c + 1) * 64; PJ_LOAD(ktn); }

        const unsigned bufoff = buf * 64 * PW * 4;
        const unsigned bufoffB = buf * 128 * PW * 4;
        #pragma unroll
        for (int ks = 0; ks < 4; ks++) {
            const int k0h = ks * 8;
            unsigned a[2][4], b[4][2];
            #pragma unroll
            for (int mf = 0; mf < 2; mf++) {
                unsigned ro = ((m_off + mf * 16 + lrowA) * PW + k0h + lkofA) * 4;
                ldsm4(a[mf], sAs0 + bufoff + ro);
            }
            #pragma unroll
            for (int nf = 0; nf < 4; nf++) {
                unsigned ro = ((n_off + nf * 8 + lrowB) * PW + k0h + lkofB) * 4;
                ldsm2(b[nf], sBt0 + bufoffB + ro);
            }
            #pragma unroll
            for (int mf = 0; mf < 2; mf++)
                #pragma unroll
                for (int nf = 0; nf < 4; nf++)
                    mma16h(acc[mf][nf], a[mf], b[nf]);
        }
        if (more) PJ_STORE(buf ^ 1);
        __syncthreads();
        buf ^= 1;
    }

    if (M == CQ) {
        #pragma unroll
        for (int mf = 0; mf < 2; mf++) {
            int r0 = m0 + m_off + mf * 16 + g;
            int r1 = r0 + 8;
            #pragma unroll
            for (int nf = 0; nf < 4; nf++) {
                int col = n0 + n_off + nf * 8 + 2 * tig;
                if (r0 < M) {
                    float b0 = bias[r0];
                    out[(size_t)col * CQ + r0]       = __float2half(acc[mf][nf][0] + b0);
                    out[(size_t)(col + 1) * CQ + r0] = __float2half(acc[mf][nf][1] + b0);
                }
                if (r1 < M) {
                    float b1 = bias[r1];
                    out[(size_t)col * CQ + r1]       = __float2half(acc[mf][nf][2] + b1);
                    out[(size_t)(col + 1) * CQ + r1] = __float2half(acc[mf][nf][3] + b1);
                }
            }
        }
    } else {
        #pragma unroll
        for (int mf = 0; mf < 2; mf++) {
            int r0 = m0 + m_off + mf * 16 + g;
            int r1 = r0 + 8;
            float b0 = bias[r0];
            float b1 = bias[r1];
            #pragma unroll
            for (int nf = 0; nf < 4; nf++) {
                int col = n0 + n_off + nf * 8 + 2 * tig;
                *(unsigned*)&out[(size_t)r0 * NPIX + col] =
                    h2u(acc[mf][nf][0] + b0, acc[mf][nf][1] + b0);
                *(unsigned*)&out[(size_t)r1 * NPIX + col] =
                    h2u(acc[mf][nf][2] + b1, acc[mf][nf][3] + b1);
            }
        }
    }
}

// ---------------------------------------------------------------------------
// energy+exp (batched z=2) — coalesced staging version (round 14, working).
// ---------------------------------------------------------------------------
__global__ void energy_exp(const __half* __restrict__ q1, const __half* __restrict__ k1,
                           __half* __restrict__ p1, float* __restrict__ ps1,
                           const __half* __restrict__ q2, const __half* __restrict__ k2,
                           __half* __restrict__ p2, float* __restrict__ ps2)
{
    __shared__ __align__(16) unsigned Qh[64 * PH];
    __shared__ __align__(16) unsigned Kh[128 * PH];
    __shared__ __align__(16) unsigned Pt[64 * PT2];
    __shared__ float rsum[64][4];

    const int z = blockIdx.z;
    const __half* q = z ? q2 : q1;
    const __half* k = z ? k2 : k1;
    __half* pm = z ? p2 : p1;
    float* ps = z ? ps2 : ps1;

    const int tid = threadIdx.x;
    const int lane = tid & 31, wid = tid >> 5;
    const int g = lane >> 2, tig = lane & 3;
    const int m_off = (wid >> 2) * 32, n_off = (wid & 3) * 32;
    const int kc = wid & 3;
    const int m0 = blockIdx.y * 64, n0 = blockIdx.x * 128;

    const int lrowA = lane & 15, lkofA = (lane & 16) ? 4 : 0;
    const int lrowB = lane & 7,  lkofB = (lane & 8) ? 4 : 0;
    const unsigned sQ = smem_u32(&Qh[0]);
    const unsigned sK = smem_u32(&Kh[0]);

    {
        int m = tid >> 2, u = tid & 3;
        *(uint4*)&Qh[m * PH + u * 4] = *(const uint4*)&q[(size_t)(m0 + m) * CQ + u * 8];
    }
    #pragma unroll
    for (int kk = 0; kk < 2; kk++) {
        int idx = tid + kk * 256;
        int n = idx >> 2, u = idx & 3;
        *(uint4*)&Kh[n * PH + u * 4] = *(const uint4*)&k[(size_t)(n0 + n) * CQ + u * 8];
    }
    __syncthreads();

    float acc[2][4][4] = {};
    #pragma unroll
    for (int ks = 0; ks < 2; ks++) {
        const int k0h = ks * 8;
        unsigned a[2][4], b[4][2];
        #pragma unroll
        for (int mf = 0; mf < 2; mf++) {
            unsigned ro = ((m_off + mf * 16 + lrowA) * PH + k0h + lkofA) * 4;
            ldsm4(a[mf], sQ + ro);
        }
        #pragma unroll
        for (int nf = 0; nf < 4; nf++) {
            unsigned ro = ((n_off + nf * 8 + lrowB) * PH + k0h + lkofB) * 4;
            ldsm2(b[nf], sK + ro);
        }
        #pragma unroll
        for (int mf = 0; mf < 2; mf++)
            #pragma unroll
            for (int nf = 0; nf < 4; nf++)
                mma16h(acc[mf][nf], a[mf], b[nf]);
    }

    float s[2][2] = {};
    #pragma unroll
    for (int mf = 0; mf < 2; mf++) {
        int lr0 = m_off + mf * 16 + g;
        int lr1 = lr0 + 8;
        #pragma unroll
        for (int nf = 0; nf < 4; nf++) {
            int cu = (n_off >> 1) + nf * 4 + tig;
            float p0 = __expf(acc[mf][nf][0] - ESH);
            float p1 = __expf(acc[mf][nf][1] - ESH);
            float p2 = __expf(acc[mf][nf][2] - ESH);
            float p3 = __expf(acc[mf][nf][3] - ESH);
            s[mf][0] += p0 + p1;
            s[mf][1] += p2 + p3;
            Pt[lr0 * PT2 + cu] = h2u(p0, p1);
            Pt[lr1 * PT2 + cu] = h2u(p2, p3);
        }
    }
    #pragma unroll
    for (int mf = 0; mf < 2; mf++) {
        #pragma unroll
        for (int j = 0; j < 2; j++) {
            s[mf][j] += __shfl_xor_sync(0xffffffffu, s[mf][j], 1);
            s[mf][j] += __shfl_xor_sync(0xffffffffu, s[mf][j], 2);
        }
    }
    if (tig == 0) {
        #pragma unroll
        for (int mf = 0; mf < 2; mf++) {
            int lr0 = m_off + mf * 16 + g;
            rsum[lr0][kc] = s[mf][0];
            rsum[lr0 + 8][kc] = s[mf][1];
        }
    }
    __syncthreads();

    #pragma unroll
    for (int kk = 0; kk < 4; kk++) {
        int idx = tid + kk * 256;
        int r = idx >> 4, u = idx & 15;
        *(uint4*)&pm[(size_t)(m0 + r) * NPIX + n0 + u * 8] = *(uint4*)&Pt[r * PT2 + u * 4];
    }
    if (tid < 64) {
        ps[(size_t)(m0 + tid) * 32 + blockIdx.x] =
            rsum[tid][0] + rsum[tid][1] + rsum[tid][2] + rsum[tid][3];
    }
}

// ---------------------------------------------------------------------------
// av fp16 (batched z=2): m 128 x n 128, lsum in prologue (round 13/14 version).
// ---------------------------------------------------------------------------
__global__ void __launch_bounds__(256, 2) av_fp16(
    const __half* __restrict__ v1, const __half* __restrict__ p1,
    const float* __restrict__ xq1, const float* __restrict__ gm1,
    const float* __restrict__ ps1,
    const __half* __restrict__ v2, const __half* __restrict__ p2,
    const float* __restrict__ xq2, const float* __restrict__ gm2,
    const float* __restrict__ ps2,
    float* __restrict__ outbase)
{
    __shared__ __align__(16) unsigned Vs[2][128 * PH];
    __shared__ __align__(16) unsigned Ps[2][128 * PH];
    __shared__ float lsm[128];

    const int z = blockIdx.z;
    const __half* vmat = z ? v2 : v1;
    const __half* pm  = z ? p2 : p1;
    const float* xq   = z ? xq2 : xq1;
    const float* gmp  = z ? gm2 : gm1;
    const float* ps   = z ? ps2 : ps1;
    float* out = outbase + (size_t)z * CC * NPIX;

    const int tid = threadIdx.x;
    const int lane = tid & 31, wid = tid >> 5;
    const int g = lane >> 2, tig = lane & 3;
    const int m_off = (wid >> 1) * 32;
    const int n_off = (wid & 1) * 64;
    const int m0 = blockIdx.y * 128, n0 = blockIdx.x * 128;

    const int lrowA = lane & 15, lkofA = (lane & 16) ? 4 : 0;
    const int lrowB = lane & 7,  lkofB = (lane & 8) ? 4 : 0;
    const unsigned sV0 = smem_u32(&Vs[0][0]);
    const unsigned sP0 = smem_u32(&Ps[0][0]);

    float acc[2][8][4] = {};

    const int row = tid >> 2, u = tid & 3;

    uint4 rV0, rV1, rP0, rP1;

    #define AV_LOAD(kt) { \
        rV0 = *(const uint4*)&vmat[(size_t)(m0 + row) * NPIX + (kt) + u * 8]; \
        rV1 = *(const uint4*)&vmat[(size_t)(m0 + row + 64) * NPIX + (kt) + u * 8]; \
        rP0 = *(const uint4*)&pm[(size_t)(n0 + row) * NPIX + (kt) + u * 8]; \
        rP1 = *(const uint4*)&pm[(size_t)(n0 + row + 64) * NPIX + (kt) + u * 8]; }

    #define AV_STORE(buf) { \
        *(uint4*)&Vs[buf][row * PH + u * 4] = rV0; \
        *(uint4*)&Vs[buf][(row + 64) * PH + u * 4] = rV1; \
        *(uint4*)&Ps[buf][row * PH + u * 4] = rP0; \
        *(uint4*)&Ps[buf][(row + 64) * PH + u * 4] = rP1; }

    {
        int col = tid >> 1, q = tid & 1;
        const float* pp = ps + (size_t)(n0 + col) * 32 + q * 16;
        float s = 0.f;
        #pragma unroll
        for (int i = 0; i < 16; i++) s += pp[i];
        s += __shfl_xor_sync(0xffffffffu, s, 1);
        if (q == 0) lsm[col] = s;
    }

    AV_LOAD(0);
    AV_STORE(0);
    __syncthreads();

    int buf = 0;
    for (int c = 0; c < NPIX / 32; c++) {
        const bool more = (c + 1 < NPIX / 32);
        if (more) { const int ktn = (c + 1) * 32; AV_LOAD(ktn); }

        const unsigned bufoff = buf * 128 * PH * 4;
        #pragma unroll
        for (int ks = 0; ks < 2; ks++) {
            const int k0h = ks * 8;
            unsigned a[2][4], b[8][2];
            #pragma unroll
            for (int mf = 0; mf < 2; mf++) {
                unsigned ro = ((m_off + mf * 16 + lrowA) * PH + k0h + lkofA) * 4;
                ldsm4(a[mf], sV0 + bufoff + ro);
            }
            #pragma unroll
            for (int nf = 0; nf < 8; nf++) {
                unsigned ro = ((n_off + nf * 8 + lrowB) * PH + k0h + lkofB) * 4;
                ldsm2(b[nf], sP0 + bufoff + ro);
            }
            #pragma unroll
            for (int mf = 0; mf < 2; mf++)
                #pragma unroll
                for (int nf = 0; nf < 8; nf++)
                    mma16h(acc[mf][nf], a[mf], b[nf]);
        }
        if (more) AV_STORE(buf ^ 1);
        __syncthreads();
        buf ^= 1;
    }

    const float gm = gmp[0];
    #pragma unroll
    for (int mf = 0; mf < 2; mf++) {
        int r0 = m0 + m_off + mf * 16 + g;
        int r1 = r0 + 8;
        #pragma unroll
        for (int nf = 0; nf < 8; nf++) {
            int lcol = n_off + nf * 8 + 2 * tig;
            int col = n0 + lcol;
            float sa = gm / lsm[lcol];
            float sb = gm / lsm[lcol + 1];
            float2 x0 = *(const float2*)&xq[r0 * NPIX + col];
            float2 x1 = *(const float2*)&xq[r1 * NPIX + col];
            *(float2*)&out[r0 * NPIX + col] =
                make_float2(acc[mf][nf][0] * sa + x0.x, acc[mf][nf][1] * sb + x0.y);
            *(float2*)&out[r1 * NPIX + col] =
                make_float2(acc[mf][nf][2] * sa + x1.x, acc[mf][nf][3] * sb + x1.y);
        }
    }
}

// ---------------------------------------------------------------------------
extern "C" void kernel_launch(void* const* d_in, const int* in_sizes, int n_in,
                              void* d_out, int out_size)
{
    const float* x1    = (const float*)d_in[0];
    const float* x2    = (const float*)d_in[1];
    const float* sx1_w = (const float*)d_in[2];
    const float* sy1_w = (const float*)d_in[3];
    const float* bn1x  = (const float*)d_in[4];
    const float* bn1y  = (const float*)d_in[5];
    const float* sx2_w = (const float*)d_in[6];
    const float* sy2_w = (const float*)d_in[7];
    const float* bn2x  = (const float*)d_in[8];
    const float* bn2y  = (const float*)d_in[9];
    const float* q1_w  = (const float*)d_in[10];
    const float* q1_b  = (const float*)d_in[11];
    const float* k1_w  = (const float*)d_in[12];
    const float* k1_b  = (const float*)d_in[13];
    const float* v1_w  = (const float*)d_in[14];
    const float* v1_b  = (const float*)d_in[15];
    const float* q2_w  = (const float*)d_in[16];
    const float* q2_b  = (const float*)d_in[17];
    const float* k2_w  = (const float*)d_in[18];
    const float* k2_b  = (const float*)d_in[19];
    const float* v2_w  = (const float*)d_in[20];
    const float* v2_b  = (const float*)d_in[21];
    const float* gamma1 = (const float*)d_in[22];
    const float* gamma2 = (const float*)d_in[23];
    float* out = (float*)d_out;

    __half *xt1, *xt2, *xfh1, *xfh2, *qh1, *kh1, *qh2, *kh2, *vh1, *vh2;
    __half *wx1h, *wy1h, *wx2h, *wy2h, *p1, *p2;
    float *ps1, *ps2;
    cudaGetSymbolAddress((void**)&xt1, g_xt1);
    cudaGetSymbolAddress((void**)&xt2, g_xt2);
    cudaGetSymbolAddress((void**)&xfh1, g_xfh1);
    cudaGetSymbolAddress((void**)&xfh2, g_xfh2);
    cudaGetSymbolAddress((void**)&qh1, g_qh1);
    cudaGetSymbolAddress((void**)&kh1, g_kh1);
    cudaGetSymbolAddress((void**)&qh2, g_qh2);
    cudaGetSymbolAddress((void**)&kh2, g_kh2);
    cudaGetSymbolAddress((void**)&vh1, g_vh1);
    cudaGetSymbolAddress((void**)&vh2, g_vh2);
    cudaGetSymbolAddress((void**)&p1, g_p1);
    cudaGetSymbolAddress((void**)&p2, g_p2);
    cudaGetSymbolAddress((void**)&ps1, g_ps1);
    cudaGetSymbolAddress((void**)&ps2, g_ps2);
    cudaGetSymbolAddress((void**)&wx1h, g_wx1h);
    cudaGetSymbolAddress((void**)&wy1h, g_wy1h);
    cudaGetSymbolAddress((void**)&wx2h, g_wx2h);
    cudaGetSymbolAddress((void**)&wy2h, g_wy2h);

    cudaFuncSetAttribute(sobel_fp16, cudaFuncAttributeMaxDynamicSharedMemorySize, SOBEL_SMEM);
    cudaFuncSetAttribute(proj_all,   cudaFuncAttributeMaxDynamicSharedMemorySize, PROJ_SMEM);

    dim3 blk(256);

    prep_kernel<<<9728, blk>>>(sx1_w, sy1_w, sx2_w, sy2_w,
                               wx1h, wy1h, wx2h, wy2h,
                               x1, x2, xt1, xt2);

    sobel_fp16<<<dim3(32, 4, 2), blk, SOBEL_SMEM>>>(
        xt1, wx1h, wy1h, bn1x, bn1y, xfh1,
        xt2, wx2h, wy2h, bn2x, bn2y, xfh2);

    ProjAll pa;
    pa.A[0] = q1_w;  pa.B[0] = xt1;  pa.bias[0] = q1_b; pa.out[0] = qh1;
    pa.A[1] = k1_w;  pa.B[1] = xfh2; pa.bias[1] = k1_b; pa.out[1] = kh1;
    pa.A[2] = q2_w;  pa.B[2] = xt2;  pa.bias[2] = q2_b; pa.out[2] = qh2;
    pa.A[3] = k2_w;  pa.B[3] = xfh1; pa.bias[3] = k2_b; pa.out[3] = kh2;
    pa.A[4] = v1_w;  pa.B[4] = xfh2; pa.bias[4] = v1_b; pa.out[4] = vh1;
    pa.A[5] = v2_w;  pa.B[5] = xfh1; pa.bias[5] = v2_b; pa.out[5] = vh2;
    proj_all<<<dim3(32, 12), blk, PROJ_SMEM>>>(pa);

    energy_exp<<<dim3(32, 64, 2), blk>>>(qh1, kh1, p1, ps1,
                                         qh2, kh2, p2, ps2);
    av_fp16<<<dim3(32, 2, 2), blk>>>(vh1, p1, x1, gamma1, ps1,
                                     vh2, p2, x2, gamma2, ps2, out);
}